// round 1
// baseline (speedup 1.0000x reference)
#include <cuda_runtime.h>
#include <math.h>
#include <float.h>

#define Bt 32
#define Pp 196
#define Dd 2048
#define Aa 512
#define Ee 512
#define Hh 512
#define Vv 10000
#define Ll 21
#define Tt 20

// output layout (float32, concatenated in return-tuple order)
#define OUT_PRED   0
#define OUT_CAPS   6400000
#define OUT_DECLEN 6400672
#define OUT_ALPHA  6400704
#define OUT_SORT   6526144

// ---------------- scratch (device globals; no runtime allocation) ----------
__device__ int   g_sort[Bt];
__device__ int   g_declen[Bt];
__device__ int   g_caps[Bt * Ll];
__device__ float g_mean[Bt * Dd];
__device__ float g_h[Bt * Hh];
__device__ float g_c[Bt * Hh];
__device__ float g_att1[Bt * Pp * Aa];     // 12.8 MB
__device__ float g_att2[Bt * Aa];
__device__ float g_gate[Bt * Dd];
__device__ float g_alpha[Bt * Pp];
__device__ float g_x[Bt * 3072];           // [emb | awe | h]
__device__ float g_part[2600000];          // split-K partial buffer

__device__ __forceinline__ float sigf(float x) { return 1.0f / (1.0f + expf(-x)); }

// ---------------- setup: stable descending argsort + caps/declen out -------
__global__ void setup_kernel(const int* __restrict__ caplen,
                             const int* __restrict__ caps_in,
                             float* __restrict__ out) {
    __shared__ int len[Bt];
    int b = threadIdx.x;
    if (b < Bt) len[b] = caplen[b];
    __syncthreads();
    if (b < Bt) {
        int myl = len[b];
        int rank = 0;
        for (int j = 0; j < Bt; j++) {
            int lj = len[j];
            if (lj > myl || (lj == myl && j < b)) rank++;
        }
        g_sort[rank] = b;
    }
    __syncthreads();
    if (b < Bt) {
        int sb = g_sort[b];
        int dl = len[sb] - 1;
        g_declen[b] = dl;
        out[OUT_SORT + b]   = (float)sb;
        out[OUT_DECLEN + b] = (float)dl;
        for (int l = 0; l < Ll; l++) {
            int tok = caps_in[sb * Ll + l];
            g_caps[b * Ll + l] = tok;
            out[OUT_CAPS + b * Ll + l] = (float)tok;
        }
    }
}

// ---------------- mean over P of sorted encoder rows -----------------------
__global__ void mean_kernel(const float* __restrict__ enc) {
    int b = blockIdx.x;
    int sb = g_sort[b];
    const float* base = enc + (size_t)sb * Pp * Dd;
    for (int d = threadIdx.x; d < Dd; d += blockDim.x) {
        float s = 0.f;
        for (int p = 0; p < Pp; p++) s += base[(size_t)p * Dd + d];
        g_mean[b * Dd + d] = s / 196.0f;
    }
}

// ---------------- att1 = enc_sorted @ enc_att_w + b  (6272x512, K=2048) ----
// tiled 64x64, BK=8, 256 threads, 4x4 register tiles
__global__ void att1_gemm(const float* __restrict__ enc,
                          const float* __restrict__ W,
                          const float* __restrict__ bias) {
    __shared__ __align__(16) float As[8][64];
    __shared__ __align__(16) float Bs[8][64];
    int tid = threadIdx.x;
    int bn = blockIdx.y * 64;

    const float* arow = enc;  // valid pointer default
    int lm = 0, lkq = 0;
    if (tid < 128) {
        lm = tid >> 1; lkq = tid & 1;
        int gm = blockIdx.x * 64 + lm;
        int b = gm / 196, p = gm - b * 196;
        arow = enc + ((size_t)g_sort[b] * Pp + p) * Dd;
    }
    int ty = tid >> 4, tx = tid & 15;

    float acc[4][4];
#pragma unroll
    for (int i = 0; i < 4; i++)
#pragma unroll
        for (int j = 0; j < 4; j++) acc[i][j] = 0.f;

    for (int k0 = 0; k0 < Dd; k0 += 8) {
        if (tid < 128) {
            float4 v = *(const float4*)(arow + k0 + lkq * 4);
            As[lkq * 4 + 0][lm] = v.x;
            As[lkq * 4 + 1][lm] = v.y;
            As[lkq * 4 + 2][lm] = v.z;
            As[lkq * 4 + 3][lm] = v.w;
        } else {
            int t2 = tid - 128;
            int kk = t2 >> 4;
            int n4 = (t2 & 15) * 4;
            *(float4*)&Bs[kk][n4] =
                *(const float4*)(W + (size_t)(k0 + kk) * Aa + bn + n4);
        }
        __syncthreads();
#pragma unroll
        for (int kk = 0; kk < 8; kk++) {
            float4 av = *(const float4*)&As[kk][ty * 4];
            float4 bv = *(const float4*)&Bs[kk][tx * 4];
            float a_[4] = {av.x, av.y, av.z, av.w};
            float b_[4] = {bv.x, bv.y, bv.z, bv.w};
#pragma unroll
            for (int i = 0; i < 4; i++)
#pragma unroll
                for (int j = 0; j < 4; j++)
                    acc[i][j] = fmaf(a_[i], b_[j], acc[i][j]);
        }
        __syncthreads();
    }
    int rm = blockIdx.x * 64 + ty * 4;
#pragma unroll
    for (int i = 0; i < 4; i++)
#pragma unroll
        for (int j = 0; j < 4; j++)
            g_att1[(size_t)(rm + i) * Aa + bn + tx * 4 + j] =
                acc[i][j] + bias[bn + tx * 4 + j];
}

// ---------------- skinny GEMM: part[ks][32][N] = X[32,Kslice] @ W ----------
// xsel: 0 = g_h, 1 = g_x, 2 = g_mean. W selection by row: k<k0rows -> W0 else W1.
__global__ void skinny_part(const float* __restrict__ W0, int k0rows,
                            const float* __restrict__ W1,
                            int K, int N, int kPer, int xsel, int partOff) {
    __shared__ __align__(16) float xs[256 * 36];
    const float* X = (xsel == 0) ? g_h : (xsel == 1) ? g_x : g_mean;
    float* part = g_part + partOff;

    int kBeg = blockIdx.y * kPer;
    int kEnd = min(K, kBeg + kPer);
    int kn = kEnd - kBeg;
    for (int i = threadIdx.x; i < 32 * kn; i += blockDim.x) {
        int m = i / kn;
        int kk = i - m * kn;
        xs[kk * 36 + m] = X[m * K + kBeg + kk];
    }
    __syncthreads();

    int n = blockIdx.x * blockDim.x + threadIdx.x;
    if (n < N) {
        float acc[32];
#pragma unroll
        for (int m = 0; m < 32; m++) acc[m] = 0.f;
        for (int k = kBeg; k < kEnd; k++) {
            float w = (k < k0rows) ? W0[(size_t)k * N + n]
                                   : W1[(size_t)(k - k0rows) * N + n];
            const float* xr = xs + (k - kBeg) * 36;
#pragma unroll
            for (int mq = 0; mq < 8; mq++) {
                float4 xv = *(const float4*)(xr + mq * 4);
                acc[mq * 4 + 0] = fmaf(xv.x, w, acc[mq * 4 + 0]);
                acc[mq * 4 + 1] = fmaf(xv.y, w, acc[mq * 4 + 1]);
                acc[mq * 4 + 2] = fmaf(xv.z, w, acc[mq * 4 + 2]);
                acc[mq * 4 + 3] = fmaf(xv.w, w, acc[mq * 4 + 3]);
            }
        }
#pragma unroll 4
        for (int m = 0; m < 32; m++)
            part[((size_t)(blockIdx.y * 32 + m)) * N + n] = acc[m];
    }
}

// ---------------- fixed-order split-K reduces (deterministic) --------------
// outsel: 0 = g_att2, 1 = g_h, 2 = g_c
__global__ void reduce_simple(int KS, int N, const float* __restrict__ bias,
                              int outsel, int partOff) {
    float* out = (outsel == 0) ? g_att2 : (outsel == 1) ? g_h : g_c;
    const float* part = g_part + partOff;
    int idx = blockIdx.x * blockDim.x + threadIdx.x;
    if (idx >= 32 * N) return;
    int m = idx / N, n = idx - m * N;
    float s = bias[n];
    for (int ks = 0; ks < KS; ks++) s += part[((size_t)(ks * 32 + m)) * N + n];
    out[m * N + n] = s;
}

__global__ void reduce_sigmoid(int KS, int N, const float* __restrict__ bias,
                               int partOff) {
    const float* part = g_part + partOff;
    int idx = blockIdx.x * blockDim.x + threadIdx.x;
    if (idx >= 32 * N) return;
    int m = idx / N, n = idx - m * N;
    float s = bias[n];
    for (int ks = 0; ks < KS; ks++) s += part[((size_t)(ks * 32 + m)) * N + n];
    g_gate[m * N + n] = sigf(s);
}

// ---------------- attention scores + softmax + masked alpha out ------------
__global__ void attn_kernel(const float* __restrict__ full_w,
                            const float* __restrict__ full_b,
                            float* __restrict__ out, int t) {
    int b = blockIdx.x;
    __shared__ __align__(16) float t2s[Aa];
    __shared__ __align__(16) float ws[Aa];
    __shared__ float es[Pp];
    __shared__ float red[2];
    int tid = threadIdx.x;
    for (int a = tid; a < Aa; a += blockDim.x) {
        t2s[a] = g_att2[b * Aa + a];
        ws[a] = full_w[a];
    }
    __syncthreads();
    int warp = tid >> 5, lane = tid & 31;
    float fb = *full_b;

    for (int p = warp; p < Pp; p += 8) {
        const float4* row = (const float4*)(g_att1 + ((size_t)(b * Pp + p)) * Aa);
        float s = 0.f;
        for (int a4 = lane; a4 < Aa / 4; a4 += 32) {
            float4 v = row[a4];
            float4 tt = *(const float4*)&t2s[a4 * 4];
            float4 w = *(const float4*)&ws[a4 * 4];
            s += fmaxf(v.x + tt.x, 0.f) * w.x;
            s += fmaxf(v.y + tt.y, 0.f) * w.y;
            s += fmaxf(v.z + tt.z, 0.f) * w.z;
            s += fmaxf(v.w + tt.w, 0.f) * w.w;
        }
#pragma unroll
        for (int o = 16; o; o >>= 1) s += __shfl_down_sync(0xffffffffu, s, o);
        if (lane == 0) es[p] = s + fb;
    }
    __syncthreads();

    if (warp == 0) {
        float mx = -FLT_MAX;
        for (int p = lane; p < Pp; p += 32) mx = fmaxf(mx, es[p]);
#pragma unroll
        for (int o = 16; o; o >>= 1)
            mx = fmaxf(mx, __shfl_xor_sync(0xffffffffu, mx, o));
        float sm = 0.f;
        for (int p = lane; p < Pp; p += 32) sm += expf(es[p] - mx);
#pragma unroll
        for (int o = 16; o; o >>= 1) sm += __shfl_xor_sync(0xffffffffu, sm, o);
        if (lane == 0) { red[0] = mx; red[1] = sm; }
    }
    __syncthreads();
    float mx = red[0], sm = red[1];
    int active = (t < g_declen[b]);
    if (tid < Pp) {
        float al = expf(es[tid] - mx) / sm;
        g_alpha[b * Pp + tid] = al;
        out[OUT_ALPHA + ((size_t)b * Tt + t) * Pp + tid] = active ? al : 0.f;
    }
}

// ---------------- awe = gate * (alpha^T @ enc) -> x[512:2560] ---------------
__global__ void awe_kernel(const float* __restrict__ enc) {
    int b = blockIdx.y;
    __shared__ float al[Pp];
    for (int p = threadIdx.x; p < Pp; p += blockDim.x) al[p] = g_alpha[b * Pp + p];
    __syncthreads();
    int d = blockIdx.x * blockDim.x + threadIdx.x;
    int sb = g_sort[b];
    const float* base = enc + (size_t)sb * Pp * Dd + d;
    float s = 0.f;
#pragma unroll 4
    for (int p = 0; p < Pp; p++) s += base[(size_t)p * Dd] * al[p];
    g_x[b * 3072 + 512 + d] = s * g_gate[b * Dd + d];
}

// ---------------- x[0:512] = emb[token], x[2560:3072] = h -------------------
__global__ void xfill_kernel(const float* __restrict__ emb, int t) {
    int i = blockIdx.x * blockDim.x + threadIdx.x;
    if (i < Bt * Ee) {
        int b = i >> 9, j = i & 511;
        int tok = g_caps[b * Ll + t];
        g_x[b * 3072 + j] = emb[(size_t)tok * Ee + j];
    } else {
        int i2 = i - Bt * Ee;
        int b = i2 >> 9, j = i2 & 511;
        g_x[b * 3072 + 2560 + j] = g_h[b * Hh + j];
    }
}

// ---------------- LSTM cell: reduce gates, update h/c with mask ------------
__global__ void reduce_lstm(const float* __restrict__ lstm_b, int t) {
    int idx = blockIdx.x * blockDim.x + threadIdx.x;  // 32*512
    int b = idx >> 9, j = idx & 511;
    float s[4];
#pragma unroll
    for (int g = 0; g < 4; g++) {
        int n = g * 512 + j;
        float acc = lstm_b[n];
        for (int ks = 0; ks < 16; ks++)
            acc += g_part[((size_t)(ks * 32 + b)) * 2048 + n];
        s[g] = acc;
    }
    float c_old = g_c[idx];
    float c_new = sigf(s[1]) * c_old + sigf(s[0]) * tanhf(s[2]);
    float h_new = sigf(s[3]) * tanhf(c_new);
    if (t < g_declen[b]) { g_c[idx] = c_new; g_h[idx] = h_new; }
}

// ---------------- fc reduce + masked prediction write ----------------------
__global__ void reduce_fc(const float* __restrict__ fc_b,
                          float* __restrict__ out, int t) {
    int idx = blockIdx.x * blockDim.x + threadIdx.x;
    if (idx >= Bt * Vv) return;
    int b = idx / Vv, n = idx - b * Vv;
    float val = 0.f;
    if (t < g_declen[b]) {
        val = fc_b[n];
#pragma unroll
        for (int ks = 0; ks < 4; ks++)
            val += g_part[((size_t)(ks * 32 + b)) * Vv + n];
    }
    out[OUT_PRED + ((size_t)b * Tt + t) * Vv + n] = val;
}

// ---------------- launch ----------------------------------------------------
extern "C" void kernel_launch(void* const* d_in, const int* in_sizes, int n_in,
                              void* d_out, int out_size) {
    const float* enc        = (const float*)d_in[0];
    const int*   caps_in    = (const int*)d_in[1];
    const int*   caplen     = (const int*)d_in[2];
    const float* enc_att_w  = (const float*)d_in[3];
    const float* enc_att_b  = (const float*)d_in[4];
    const float* dec_att_w  = (const float*)d_in[5];
    const float* dec_att_b  = (const float*)d_in[6];
    const float* full_att_w = (const float*)d_in[7];
    const float* full_att_b = (const float*)d_in[8];
    const float* emb        = (const float*)d_in[9];
    const float* init_h_w   = (const float*)d_in[10];
    const float* init_h_b   = (const float*)d_in[11];
    const float* init_c_w   = (const float*)d_in[12];
    const float* init_c_b   = (const float*)d_in[13];
    const float* f_beta_w   = (const float*)d_in[14];
    const float* f_beta_b   = (const float*)d_in[15];
    const float* lstm_w_ih  = (const float*)d_in[16];
    const float* lstm_w_hh  = (const float*)d_in[17];
    const float* lstm_b     = (const float*)d_in[18];
    const float* fc_w       = (const float*)d_in[19];
    const float* fc_b       = (const float*)d_in[20];
    float* out = (float*)d_out;

    const int REG1 = 1310720;  // second partial-buffer region

    setup_kernel<<<1, 32>>>(caplen, caps_in, out);
    mean_kernel<<<32, 256>>>(enc);

    // h0 = mean @ init_h_w + b ; c0 likewise (K=2048, N=512, KS=8)
    skinny_part<<<dim3(2, 8), 256>>>(init_h_w, 2048, init_h_w, 2048, 512, 256, 2, 0);
    reduce_simple<<<64, 256>>>(8, 512, init_h_b, 1, 0);
    skinny_part<<<dim3(2, 8), 256>>>(init_c_w, 2048, init_c_w, 2048, 512, 256, 2, 0);
    reduce_simple<<<64, 256>>>(8, 512, init_c_b, 2, 0);

    // att1 = enc_sorted @ enc_att_w + b   (6272 x 512, K=2048)
    att1_gemm<<<dim3(98, 8), 256>>>(enc, enc_att_w, enc_att_b);

    for (int t = 0; t < Tt; t++) {
        // att2 = h @ dec_att_w + b     (K=512, N=512, KS=4)
        skinny_part<<<dim3(2, 4), 256>>>(dec_att_w, 512, dec_att_w, 512, 512, 128, 0, 0);
        reduce_simple<<<64, 256>>>(4, 512, dec_att_b, 0, 0);
        // gate = sigmoid(h @ f_beta_w + b)   (K=512, N=2048, KS=4)
        skinny_part<<<dim3(8, 4), 256>>>(f_beta_w, 512, f_beta_w, 512, 2048, 128, 0, REG1);
        reduce_sigmoid<<<256, 256>>>(4, 2048, f_beta_b, REG1);
        // e, softmax, alpha (masked write)
        attn_kernel<<<32, 256>>>(full_att_w, full_att_b, out, t);
        // awe into x[512:2560]
        awe_kernel<<<dim3(8, 32), 256>>>(enc);
        // emb + h into x
        xfill_kernel<<<128, 256>>>(emb, t);
        // gates = x @ [w_ih; w_hh]    (K=3072, N=2048, KS=16)
        skinny_part<<<dim3(8, 16), 256>>>(lstm_w_ih, 2560, lstm_w_hh, 3072, 2048, 192, 1, 0);
        reduce_lstm<<<64, 256>>>(lstm_b, t);
        // preds = h_new @ fc_w + b    (K=512, N=10000, KS=4)
        skinny_part<<<dim3(40, 4), 256>>>(fc_w, 512, fc_w, 512, 10000, 128, 0, 0);
        reduce_fc<<<1250, 256>>>(fc_b, out, t);
    }
}

// round 2
// speedup vs baseline: 1.6869x; 1.6869x over previous
#include <cuda_runtime.h>
#include <math.h>
#include <float.h>

#define Bt 32
#define Pp 196
#define Dd 2048
#define Aa 512
#define Ee 512
#define Hh 512
#define Vv 10000
#define Ll 21
#define Tt 20

// output layout (float32, concatenated in return-tuple order)
#define OUT_PRED   0
#define OUT_CAPS   6400000
#define OUT_DECLEN 6400672
#define OUT_ALPHA  6400704
#define OUT_SORT   6526144

// ---------------- scratch (device globals; no runtime allocation) ----------
__device__ int   g_sort[Bt];
__device__ int   g_declen[Bt];
__device__ int   g_caps[Bt * Ll];
__device__ float g_mean[Bt * Dd];
__device__ float g_h[Bt * Hh];
__device__ float g_c[Bt * Hh];
__device__ float g_att1[Bt * Pp * Aa];     // 12.8 MB
__device__ float g_att2[Bt * Aa];
__device__ float g_gate[Bt * Dd];
__device__ float g_alpha[Bt * Pp];
__device__ float g_x[Bt * 3072];           // [emb | awe | h]
__device__ float g_embs[Bt * Tt * Ee];     // all embeddings, gathered once
__device__ float g_hall[Tt * Bt * Hh];     // h_new per step (for deferred fc)
__device__ float g_part[2600000];          // split-K partial buffer

__device__ __forceinline__ float sigf(float x) { return 1.0f / (1.0f + expf(-x)); }

// ---------------- setup: stable descending argsort + caps/declen out -------
__global__ void setup_kernel(const int* __restrict__ caplen,
                             const int* __restrict__ caps_in,
                             float* __restrict__ out) {
    __shared__ int len[Bt];
    int b = threadIdx.x;
    if (b < Bt) len[b] = caplen[b];
    __syncthreads();
    if (b < Bt) {
        int myl = len[b];
        int rank = 0;
        for (int j = 0; j < Bt; j++) {
            int lj = len[j];
            if (lj > myl || (lj == myl && j < b)) rank++;
        }
        g_sort[rank] = b;
    }
    __syncthreads();
    if (b < Bt) {
        int sb = g_sort[b];
        int dl = len[sb] - 1;
        g_declen[b] = dl;
        out[OUT_SORT + b]   = (float)sb;
        out[OUT_DECLEN + b] = (float)dl;
        for (int l = 0; l < Ll; l++) {
            int tok = caps_in[sb * Ll + l];
            g_caps[b * Ll + l] = tok;
            out[OUT_CAPS + b * Ll + l] = (float)tok;
        }
    }
}

// ---------------- gather ALL embeddings once; seed x emb part for t=0 ------
__global__ void emb_gather(const float* __restrict__ emb) {
    int i = blockIdx.x * blockDim.x + threadIdx.x;   // 32*20*512
    if (i >= Bt * Tt * Ee) return;
    int b = i / (Tt * Ee);
    int r = i - b * (Tt * Ee);
    int t = r >> 9;
    int j = r & 511;
    int tok = g_caps[b * Ll + t];
    float v = emb[(size_t)tok * Ee + j];
    g_embs[i] = v;
    if (t == 0) g_x[b * 3072 + j] = v;
}

// ---------------- mean over P of sorted encoder rows -----------------------
__global__ void mean_kernel(const float* __restrict__ enc) {
    int b = blockIdx.x;
    int sb = g_sort[b];
    const float* base = enc + (size_t)sb * Pp * Dd;
    for (int d = threadIdx.x; d < Dd; d += blockDim.x) {
        float s = 0.f;
        for (int p = 0; p < Pp; p++) s += base[(size_t)p * Dd + d];
        g_mean[b * Dd + d] = s / 196.0f;
    }
}

// ---------------- generic skinny split-K: part[ks][32][N] = X @ W ----------
// xsel: 0 = g_h, 1 = g_x, 2 = g_mean. W row k: k<k0rows -> W0 else W1.
__global__ void skinny_part(const float* __restrict__ W0, int k0rows,
                            const float* __restrict__ W1,
                            int K, int N, int kPer, int xsel, int partOff) {
    __shared__ __align__(16) float xs[256 * 36];
    const float* X = (xsel == 0) ? g_h : (xsel == 1) ? g_x : g_mean;
    float* part = g_part + partOff;

    int kBeg = blockIdx.y * kPer;
    int kEnd = min(K, kBeg + kPer);
    int kn = kEnd - kBeg;
    for (int i = threadIdx.x; i < 32 * kn; i += blockDim.x) {
        int m = i / kn;
        int kk = i - m * kn;
        xs[kk * 36 + m] = X[m * K + kBeg + kk];
    }
    __syncthreads();

    int n = blockIdx.x * blockDim.x + threadIdx.x;
    if (n < N) {
        float acc[32];
#pragma unroll
        for (int m = 0; m < 32; m++) acc[m] = 0.f;
        for (int k = kBeg; k < kEnd; k++) {
            float w = (k < k0rows) ? W0[(size_t)k * N + n]
                                   : W1[(size_t)(k - k0rows) * N + n];
            const float* xr = xs + (k - kBeg) * 36;
#pragma unroll
            for (int mq = 0; mq < 8; mq++) {
                float4 xv = *(const float4*)(xr + mq * 4);
                acc[mq * 4 + 0] = fmaf(xv.x, w, acc[mq * 4 + 0]);
                acc[mq * 4 + 1] = fmaf(xv.y, w, acc[mq * 4 + 1]);
                acc[mq * 4 + 2] = fmaf(xv.z, w, acc[mq * 4 + 2]);
                acc[mq * 4 + 3] = fmaf(xv.w, w, acc[mq * 4 + 3]);
            }
        }
#pragma unroll 4
        for (int m = 0; m < 32; m++)
            part[((size_t)(blockIdx.y * 32 + m)) * N + n] = acc[m];
    }
}

// ---------------- h0/c0 reduce. outsel: 1 = g_h (also seeds x), 2 = g_c ----
__global__ void reduce_simple(int KS, int N, const float* __restrict__ bias,
                              int outsel, int partOff) {
    const float* part = g_part + partOff;
    int idx = blockIdx.x * blockDim.x + threadIdx.x;
    if (idx >= 32 * N) return;
    int m = idx / N, n = idx - m * N;
    float s = bias[n];
    for (int ks = 0; ks < KS; ks++) s += part[((size_t)(ks * 32 + m)) * N + n];
    if (outsel == 1) {
        g_h[m * N + n] = s;
        g_x[m * 3072 + 2560 + n] = s;
    } else {
        g_c[m * N + n] = s;
    }
}

// ---------------- fused hproj: [att2 | gate_pre] = h @ [dec_att_w | f_beta_w]
// K=512, N=2560, split-K KS=4, kPer=128
__global__ void hproj_part(const float* __restrict__ dec_att_w,
                           const float* __restrict__ f_beta_w) {
    __shared__ __align__(16) float xs[128 * 36];
    int kBeg = blockIdx.y * 128;
    for (int i = threadIdx.x; i < 32 * 128; i += blockDim.x) {
        int m = i >> 7;
        int kk = i & 127;
        xs[kk * 36 + m] = g_h[m * 512 + kBeg + kk];
    }
    __syncthreads();

    int n = blockIdx.x * blockDim.x + threadIdx.x;   // < 2560
    const float* Wp;
    int stride;
    if (n < 512) { Wp = dec_att_w + n; stride = 512; }
    else         { Wp = f_beta_w + (n - 512); stride = 2048; }

    float acc[32];
#pragma unroll
    for (int m = 0; m < 32; m++) acc[m] = 0.f;
    for (int kk = 0; kk < 128; kk++) {
        float w = Wp[(size_t)(kBeg + kk) * stride];
        const float* xr = xs + kk * 36;
#pragma unroll
        for (int mq = 0; mq < 8; mq++) {
            float4 xv = *(const float4*)(xr + mq * 4);
            acc[mq * 4 + 0] = fmaf(xv.x, w, acc[mq * 4 + 0]);
            acc[mq * 4 + 1] = fmaf(xv.y, w, acc[mq * 4 + 1]);
            acc[mq * 4 + 2] = fmaf(xv.z, w, acc[mq * 4 + 2]);
            acc[mq * 4 + 3] = fmaf(xv.w, w, acc[mq * 4 + 3]);
        }
    }
#pragma unroll 4
    for (int m = 0; m < 32; m++)
        g_part[((size_t)(blockIdx.y * 32 + m)) * 2560 + n] = acc[m];
}

__global__ void reduce_hproj(const float* __restrict__ dec_att_b,
                             const float* __restrict__ f_beta_b) {
    int idx = blockIdx.x * blockDim.x + threadIdx.x;   // 32*2560
    if (idx >= 32 * 2560) return;
    int m = idx / 2560, n = idx - m * 2560;
    float s = 0.f;
#pragma unroll
    for (int ks = 0; ks < 4; ks++) s += g_part[((size_t)(ks * 32 + m)) * 2560 + n];
    if (n < 512) g_att2[m * 512 + n] = s + dec_att_b[n];
    else         g_gate[m * 2048 + (n - 512)] = sigf(s + f_beta_b[n - 512]);
}

// ---------------- attention scores + softmax + masked alpha out ------------
__global__ void attn_kernel(const float* __restrict__ full_w,
                            const float* __restrict__ full_b,
                            float* __restrict__ out, int t) {
    int b = blockIdx.x;
    __shared__ __align__(16) float t2s[Aa];
    __shared__ __align__(16) float ws[Aa];
    __shared__ float es[Pp];
    __shared__ float red[2];
    int tid = threadIdx.x;
    for (int a = tid; a < Aa; a += blockDim.x) {
        t2s[a] = g_att2[b * Aa + a];
        ws[a] = full_w[a];
    }
    __syncthreads();
    int warp = tid >> 5, lane = tid & 31;
    float fb = *full_b;

    for (int p = warp; p < Pp; p += 8) {
        const float4* row = (const float4*)(g_att1 + ((size_t)(b * Pp + p)) * Aa);
        float s = 0.f;
        for (int a4 = lane; a4 < Aa / 4; a4 += 32) {
            float4 v = row[a4];
            float4 tt = *(const float4*)&t2s[a4 * 4];
            float4 w = *(const float4*)&ws[a4 * 4];
            s += fmaxf(v.x + tt.x, 0.f) * w.x;
            s += fmaxf(v.y + tt.y, 0.f) * w.y;
            s += fmaxf(v.z + tt.z, 0.f) * w.z;
            s += fmaxf(v.w + tt.w, 0.f) * w.w;
        }
#pragma unroll
        for (int o = 16; o; o >>= 1) s += __shfl_down_sync(0xffffffffu, s, o);
        if (lane == 0) es[p] = s + fb;
    }
    __syncthreads();

    if (warp == 0) {
        float mx = -FLT_MAX;
        for (int p = lane; p < Pp; p += 32) mx = fmaxf(mx, es[p]);
#pragma unroll
        for (int o = 16; o; o >>= 1)
            mx = fmaxf(mx, __shfl_xor_sync(0xffffffffu, mx, o));
        float sm = 0.f;
        for (int p = lane; p < Pp; p += 32) sm += expf(es[p] - mx);
#pragma unroll
        for (int o = 16; o; o >>= 1) sm += __shfl_xor_sync(0xffffffffu, sm, o);
        if (lane == 0) { red[0] = mx; red[1] = sm; }
    }
    __syncthreads();
    float mx = red[0], sm = red[1];
    int active = (t < g_declen[b]);
    if (tid < Pp) {
        float al = expf(es[tid] - mx) / sm;
        g_alpha[b * Pp + tid] = al;
        out[OUT_ALPHA + ((size_t)b * Tt + t) * Pp + tid] = active ? al : 0.f;
    }
}

// ---------------- awe = gate * (alpha^T @ enc) -> x[512:2560] ---------------
__global__ void awe_kernel(const float* __restrict__ enc) {
    int b = blockIdx.y;
    __shared__ float al[Pp];
    for (int p = threadIdx.x; p < Pp; p += blockDim.x) al[p] = g_alpha[b * Pp + p];
    __syncthreads();
    int d = blockIdx.x * blockDim.x + threadIdx.x;
    int sb = g_sort[b];
    const float* base = enc + (size_t)sb * Pp * Dd + d;
    float s = 0.f;
#pragma unroll 4
    for (int p = 0; p < Pp; p++) s += base[(size_t)p * Dd] * al[p];
    g_x[b * 3072 + 512 + d] = s * g_gate[b * Dd + d];
}

// ---------------- LSTM cell: reduce gates, update h/c, feed next step ------
__global__ void reduce_lstm_cell(const float* __restrict__ lstm_b, int t) {
    int idx = blockIdx.x * blockDim.x + threadIdx.x;  // 32*512
    int b = idx >> 9, j = idx & 511;
    float s[4];
#pragma unroll
    for (int g = 0; g < 4; g++) {
        int n = g * 512 + j;
        float acc = lstm_b[n];
        for (int ks = 0; ks < 16; ks++)
            acc += g_part[((size_t)(ks * 32 + b)) * 2048 + n];
        s[g] = acc;
    }
    float c_old = g_c[idx];
    float c_new = sigf(s[1]) * c_old + sigf(s[0]) * tanhf(s[2]);
    float h_new = sigf(s[3]) * tanhf(c_new);
    // h for deferred fc (unmasked; fc output masks)
    g_hall[((size_t)t * Bt + b) * Hh + j] = h_new;
    int active = (t < g_declen[b]);
    float h_keep = active ? h_new : g_h[idx];
    float c_keep = active ? c_new : c_old;
    g_h[idx] = h_keep;
    g_c[idx] = c_keep;
    // feed next step's x: h part + emb part
    g_x[b * 3072 + 2560 + j] = h_keep;
    if (t + 1 < Tt)
        g_x[b * 3072 + j] = g_embs[((size_t)b * Tt + (t + 1)) * Ee + j];
}

// ---------------- att1 = enc_sorted @ enc_att_w + b  (6272x512, K=2048) ----
// tile 128x64, BK=16, 256 threads, 8x4 register tiles
__global__ void att1_gemm(const float* __restrict__ enc,
                          const float* __restrict__ W,
                          const float* __restrict__ bias) {
    __shared__ __align__(16) float As[16][128];
    __shared__ __align__(16) float Bs[16][64];
    int tid = threadIdx.x;
    int bn = blockIdx.y * 64;

    int lm = tid & 127;
    int kq = tid >> 7;            // 0 or 1
    int gm = blockIdx.x * 128 + lm;
    int bb = gm / 196, pp = gm - bb * 196;
    const float* arow = enc + ((size_t)g_sort[bb] * Pp + pp) * Dd;

    int bkk = tid >> 4;           // 0..15
    int bn4 = (tid & 15) * 4;

    int ty = tid >> 4, tx = tid & 15;

    float acc[8][4];
#pragma unroll
    for (int i = 0; i < 8; i++)
#pragma unroll
        for (int j = 0; j < 4; j++) acc[i][j] = 0.f;

    for (int k0 = 0; k0 < Dd; k0 += 16) {
        float4 v1 = *(const float4*)(arow + k0 + kq * 4);
        float4 v2 = *(const float4*)(arow + k0 + kq * 4 + 8);
        As[kq * 4 + 0][lm] = v1.x;
        As[kq * 4 + 1][lm] = v1.y;
        As[kq * 4 + 2][lm] = v1.z;
        As[kq * 4 + 3][lm] = v1.w;
        As[kq * 4 + 8][lm] = v2.x;
        As[kq * 4 + 9][lm] = v2.y;
        As[kq * 4 + 10][lm] = v2.z;
        As[kq * 4 + 11][lm] = v2.w;
        *(float4*)&Bs[bkk][bn4] =
            *(const float4*)(W + (size_t)(k0 + bkk) * Aa + bn + bn4);
        __syncthreads();
#pragma unroll
        for (int kk = 0; kk < 16; kk++) {
            float4 a0 = *(const float4*)&As[kk][ty * 8];
            float4 a1 = *(const float4*)&As[kk][ty * 8 + 4];
            float4 bv = *(const float4*)&Bs[kk][tx * 4];
            float a_[8] = {a0.x, a0.y, a0.z, a0.w, a1.x, a1.y, a1.z, a1.w};
            float b_[4] = {bv.x, bv.y, bv.z, bv.w};
#pragma unroll
            for (int i = 0; i < 8; i++)
#pragma unroll
                for (int j = 0; j < 4; j++)
                    acc[i][j] = fmaf(a_[i], b_[j], acc[i][j]);
        }
        __syncthreads();
    }
    int rm = blockIdx.x * 128 + ty * 8;
#pragma unroll
    for (int i = 0; i < 8; i++)
#pragma unroll
        for (int j = 0; j < 4; j++)
            g_att1[(size_t)(rm + i) * Aa + bn + tx * 4 + j] =
                acc[i][j] + bias[bn + tx * 4 + j];
}

// ---------------- deferred fc: preds = h_all @ fc_w + b, masked ------------
// M=640 (m = t*32+b), N=10000, K=512. tile 64x64, BK=16, 4x4 micro.
__global__ void fc_gemm(const float* __restrict__ fc_w,
                        const float* __restrict__ fc_b,
                        float* __restrict__ out) {
    __shared__ __align__(16) float As[16][64];
    __shared__ __align__(16) float Bs[16][64];
    int tid = threadIdx.x;
    int bm = blockIdx.x * 64;
    int bn = blockIdx.y * 64;

    int lm = tid & 63;
    int kq = tid >> 6;            // 0..3
    const float* arow = g_hall + (size_t)(bm + lm) * Hh;

    int bkk = tid >> 4;
    int bn4 = (tid & 15) * 4;

    int ty = tid >> 4, tx = tid & 15;

    float acc[4][4];
#pragma unroll
    for (int i = 0; i < 4; i++)
#pragma unroll
        for (int j = 0; j < 4; j++) acc[i][j] = 0.f;

    for (int k0 = 0; k0 < Hh; k0 += 16) {
        float4 v = *(const float4*)(arow + k0 + kq * 4);
        As[kq * 4 + 0][lm] = v.x;
        As[kq * 4 + 1][lm] = v.y;
        As[kq * 4 + 2][lm] = v.z;
        As[kq * 4 + 3][lm] = v.w;
        int gn = bn + bn4;
        if (gn < Vv) {
            *(float4*)&Bs[bkk][bn4] =
                *(const float4*)(fc_w + (size_t)(k0 + bkk) * Vv + gn);
        } else {
            Bs[bkk][bn4] = 0.f; Bs[bkk][bn4 + 1] = 0.f;
            Bs[bkk][bn4 + 2] = 0.f; Bs[bkk][bn4 + 3] = 0.f;
        }
        __syncthreads();
#pragma unroll
        for (int kk = 0; kk < 16; kk++) {
            float4 av = *(const float4*)&As[kk][ty * 4];
            float4 bv = *(const float4*)&Bs[kk][tx * 4];
            float a_[4] = {av.x, av.y, av.z, av.w};
            float b_[4] = {bv.x, bv.y, bv.z, bv.w};
#pragma unroll
            for (int i = 0; i < 4; i++)
#pragma unroll
                for (int j = 0; j < 4; j++)
                    acc[i][j] = fmaf(a_[i], b_[j], acc[i][j]);
        }
        __syncthreads();
    }
    int gn0 = bn + tx * 4;
    if (gn0 >= Vv) return;
#pragma unroll
    for (int i = 0; i < 4; i++) {
        int m = bm + ty * 4 + i;       // m = t*32 + b
        int t = m >> 5, b = m & 31;
        int active = (t < g_declen[b]);
        size_t obase = OUT_PRED + ((size_t)b * Tt + t) * Vv + gn0;
#pragma unroll
        for (int j = 0; j < 4; j++) {
            float val = active ? (acc[i][j] + fc_b[gn0 + j]) : 0.f;
            out[obase + j] = val;
        }
    }
}

// ---------------- launch ----------------------------------------------------
extern "C" void kernel_launch(void* const* d_in, const int* in_sizes, int n_in,
                              void* d_out, int out_size) {
    const float* enc        = (const float*)d_in[0];
    const int*   caps_in    = (const int*)d_in[1];
    const int*   caplen     = (const int*)d_in[2];
    const float* enc_att_w  = (const float*)d_in[3];
    const float* enc_att_b  = (const float*)d_in[4];
    const float* dec_att_w  = (const float*)d_in[5];
    const float* dec_att_b  = (const float*)d_in[6];
    const float* full_att_w = (const float*)d_in[7];
    const float* full_att_b = (const float*)d_in[8];
    const float* emb        = (const float*)d_in[9];
    const float* init_h_w   = (const float*)d_in[10];
    const float* init_h_b   = (const float*)d_in[11];
    const float* init_c_w   = (const float*)d_in[12];
    const float* init_c_b   = (const float*)d_in[13];
    const float* f_beta_w   = (const float*)d_in[14];
    const float* f_beta_b   = (const float*)d_in[15];
    const float* lstm_w_ih  = (const float*)d_in[16];
    const float* lstm_w_hh  = (const float*)d_in[17];
    const float* lstm_b     = (const float*)d_in[18];
    const float* fc_w       = (const float*)d_in[19];
    const float* fc_b       = (const float*)d_in[20];
    float* out = (float*)d_out;

    setup_kernel<<<1, 32>>>(caplen, caps_in, out);
    emb_gather<<<1280, 256>>>(emb);
    mean_kernel<<<32, 256>>>(enc);

    // h0 = mean @ init_h_w + b ; c0 likewise (K=2048, N=512, KS=8)
    skinny_part<<<dim3(2, 8), 256>>>(init_h_w, 2048, init_h_w, 2048, 512, 256, 2, 0);
    reduce_simple<<<64, 256>>>(8, 512, init_h_b, 1, 0);
    skinny_part<<<dim3(2, 8), 256>>>(init_c_w, 2048, init_c_w, 2048, 512, 256, 2, 0);
    reduce_simple<<<64, 256>>>(8, 512, init_c_b, 2, 0);

    // att1 = enc_sorted @ enc_att_w + b   (6272 x 512, K=2048)
    att1_gemm<<<dim3(49, 8), 256>>>(enc, enc_att_w, enc_att_b);

    for (int t = 0; t < Tt; t++) {
        // [att2 | gate] = h @ [dec_att_w | f_beta_w]   (K=512, N=2560, KS=4)
        hproj_part<<<dim3(10, 4), 256>>>(dec_att_w, f_beta_w);
        reduce_hproj<<<320, 256>>>(dec_att_b, f_beta_b);
        // e, softmax, alpha (masked write)
        attn_kernel<<<32, 256>>>(full_att_w, full_att_b, out, t);
        // awe into x[512:2560]
        awe_kernel<<<dim3(8, 32), 256>>>(enc);
        // gates = x @ [w_ih; w_hh]    (K=3072, N=2048, KS=16)
        skinny_part<<<dim3(8, 16), 256>>>(lstm_w_ih, 2560, lstm_w_hh, 3072, 2048, 192, 1, 0);
        reduce_lstm_cell<<<64, 256>>>(lstm_b, t);
        // fc deferred: h_new stored in g_hall by reduce_lstm_cell
    }

    // preds = h_all @ fc_w + b (masked), one big GEMM after the loop
    fc_gemm<<<dim3(10, 157), 256>>>(fc_w, fc_b, out);
}

// round 3
// speedup vs baseline: 3.2686x; 1.9376x over previous
#include <cuda_runtime.h>
#include <math.h>
#include <float.h>

#define Bt 32
#define Pp 196
#define Dd 2048
#define Aa 512
#define Ee 512
#define Hh 512
#define Vv 10000
#define Ll 21
#define Tt 20

// output layout (float32, concatenated in return-tuple order)
#define OUT_PRED   0
#define OUT_CAPS   6400000
#define OUT_DECLEN 6400672
#define OUT_ALPHA  6400704
#define OUT_SORT   6526144

typedef unsigned long long ull;

// ---------------- packed f32x2 helpers --------------------------------------
__device__ __forceinline__ ull pk2(float x) {
    ull r; asm("mov.b64 %0, {%1, %1};" : "=l"(r) : "f"(x)); return r;
}
__device__ __forceinline__ void fm2(ull& d, ull a, ull b) {
    asm("fma.rn.f32x2 %0, %1, %2, %0;" : "+l"(d) : "l"(a), "l"(b));
}
__device__ __forceinline__ float2 up2(ull v) {
    float2 r; asm("mov.b64 {%0, %1}, %2;" : "=f"(r.x), "=f"(r.y) : "l"(v)); return r;
}

// ---------------- scratch (device globals; no runtime allocation) ----------
__device__ int   g_sort[Bt];
__device__ int   g_declen[Bt];
__device__ int   g_caps[Bt * Ll];
__device__ float g_mean[Bt * Dd];
__device__ float g_h[Bt * Hh];
__device__ float g_c[Bt * Hh];
__device__ float g_att1[Bt * Pp * Aa];     // 12.8 MB
__device__ float g_alpha[Bt * Pp];
__device__ float g_x[Bt * 3072];           // [emb | awe | h]
__device__ float g_embs[Bt * Tt * Ee];     // all embeddings, gathered once
__device__ float g_hall[Tt * Bt * Hh];     // h_new per step (for deferred fc)
__device__ float g_part[2600000];          // split-K partial buffer

__device__ __forceinline__ float sigf(float x) { return 1.0f / (1.0f + expf(-x)); }

// ---------------- setup: stable descending argsort + caps/declen out -------
__global__ void setup_kernel(const int* __restrict__ caplen,
                             const int* __restrict__ caps_in,
                             float* __restrict__ out) {
    __shared__ int len[Bt];
    int b = threadIdx.x;
    if (b < Bt) len[b] = caplen[b];
    __syncthreads();
    if (b < Bt) {
        int myl = len[b];
        int rank = 0;
        for (int j = 0; j < Bt; j++) {
            int lj = len[j];
            if (lj > myl || (lj == myl && j < b)) rank++;
        }
        g_sort[rank] = b;
    }
    __syncthreads();
    if (b < Bt) {
        int sb = g_sort[b];
        int dl = len[sb] - 1;
        g_declen[b] = dl;
        out[OUT_SORT + b]   = (float)sb;
        out[OUT_DECLEN + b] = (float)dl;
        for (int l = 0; l < Ll; l++) {
            int tok = caps_in[sb * Ll + l];
            g_caps[b * Ll + l] = tok;
            out[OUT_CAPS + b * Ll + l] = (float)tok;
        }
    }
}

// ---------------- gather ALL embeddings once; seed x emb part for t=0 ------
__global__ void emb_gather(const float* __restrict__ emb) {
    int i = blockIdx.x * blockDim.x + threadIdx.x;   // 32*20*512
    if (i >= Bt * Tt * Ee) return;
    int b = i / (Tt * Ee);
    int r = i - b * (Tt * Ee);
    int t = r >> 9;
    int j = r & 511;
    int tok = g_caps[b * Ll + t];
    float v = emb[(size_t)tok * Ee + j];
    g_embs[i] = v;
    if (t == 0) g_x[b * 3072 + j] = v;
}

// ---------------- mean over P of sorted encoder rows -----------------------
__global__ void mean_kernel(const float* __restrict__ enc) {
    int b = blockIdx.x;
    int sb = g_sort[b];
    const float* base = enc + (size_t)sb * Pp * Dd;
    for (int d = threadIdx.x; d < Dd; d += blockDim.x) {
        float s0 = 0.f, s1 = 0.f;
        for (int p = 0; p < Pp; p += 2) {
            s0 += base[(size_t)p * Dd + d];
            s1 += base[(size_t)(p + 1) * Dd + d];
        }
        g_mean[b * Dd + d] = (s0 + s1) / 196.0f;
    }
}

// ---------------- unified skinny split-K GEMM, f32x2 packed -----------------
// part[ksBlock*32+m][N] = X[32, kslice] @ W
// weight resolution: if kBeg >= kSplit -> WB (rows offset by kSplit, stride sB)
//                    else if n < nSplit -> WA (stride sA) else WC (stride sC)
// xsel: 0 = g_h, 1 = g_x, 2 = g_mean. K = X row stride.
__global__ void skinny2(const float* __restrict__ WA, int sA,
                        const float* __restrict__ WC, int sC, int nSplit,
                        const float* __restrict__ WB, int sB, int kSplit,
                        int K, int N, int kPer, int xsel) {
    __shared__ __align__(16) float xs[128 * 34];
    const float* X = (xsel == 0) ? g_h : (xsel == 1) ? g_x : g_mean;
    int kBeg = blockIdx.y * kPer;

    // coalesced X load: i = m*kPer + kk
    for (int i = threadIdx.x; i < 32 * kPer; i += 256) {
        int m = i / kPer;
        int kk = i - m * kPer;
        xs[kk * 34 + m] = X[m * K + kBeg + kk];
    }
    __syncthreads();

    int n = blockIdx.x * 256 + threadIdx.x;
    if (n >= N) return;

    const float* W; int st;
    if (kBeg >= kSplit) {
        W = WB + (size_t)(kBeg - kSplit) * sB + n; st = sB;
    } else if (n < nSplit) {
        W = WA + (size_t)kBeg * sA + n; st = sA;
    } else {
        W = WC + (size_t)kBeg * sC + (n - nSplit); st = sC;
    }

    ull acc[16];
#pragma unroll
    for (int i = 0; i < 16; i++) acc[i] = 0ULL;

#pragma unroll 1
    for (int kk = 0; kk < kPer; kk += 4) {
        float w0 = W[(size_t)(kk + 0) * st];
        float w1 = W[(size_t)(kk + 1) * st];
        float w2 = W[(size_t)(kk + 2) * st];
        float w3 = W[(size_t)(kk + 3) * st];
        const ull* x0 = (const ull*)(xs + (kk + 0) * 34);
        const ull* x1 = (const ull*)(xs + (kk + 1) * 34);
        const ull* x2 = (const ull*)(xs + (kk + 2) * 34);
        const ull* x3 = (const ull*)(xs + (kk + 3) * 34);
        ull wp;
        wp = pk2(w0);
#pragma unroll
        for (int i = 0; i < 16; i++) fm2(acc[i], x0[i], wp);
        wp = pk2(w1);
#pragma unroll
        for (int i = 0; i < 16; i++) fm2(acc[i], x1[i], wp);
        wp = pk2(w2);
#pragma unroll
        for (int i = 0; i < 16; i++) fm2(acc[i], x2[i], wp);
        wp = pk2(w3);
#pragma unroll
        for (int i = 0; i < 16; i++) fm2(acc[i], x3[i], wp);
    }

    float* prow = g_part + ((size_t)(blockIdx.y * 32)) * N + n;
#pragma unroll
    for (int mp = 0; mp < 16; mp++) {
        float2 v = up2(acc[mp]);
        prow[(size_t)(2 * mp) * N]     = v.x;
        prow[(size_t)(2 * mp + 1) * N] = v.y;
    }
}

// ---------------- fused h0/c0 reduce (N=1024, KS=16) ------------------------
__global__ void reduce_init_hc(const float* __restrict__ init_h_b,
                               const float* __restrict__ init_c_b) {
    int idx = blockIdx.x * blockDim.x + threadIdx.x;   // 32*1024
    if (idx >= 32 * 1024) return;
    int m = idx >> 10, n = idx & 1023;
    float s = 0.f;
#pragma unroll
    for (int ks = 0; ks < 16; ks++) s += g_part[((size_t)(ks * 32 + m)) * 1024 + n];
    if (n < 512) {
        float v = s + init_h_b[n];
        g_h[m * 512 + n] = v;
        g_x[m * 3072 + 2560 + n] = v;
    } else {
        g_c[m * 512 + (n - 512)] = s + init_c_b[n - 512];
    }
}

// ---------------- attention: att2 reduce + scores + softmax + alpha --------
// 512 threads per block, one block per b. hproj parts: KS=8, N=2560.
__global__ void attn_kernel(const float* __restrict__ dec_att_b,
                            const float* __restrict__ full_w,
                            const float* __restrict__ full_b,
                            float* __restrict__ out, int t) {
    int b = blockIdx.x;
    __shared__ __align__(16) float t2s[Aa];
    __shared__ __align__(16) float ws[Aa];
    __shared__ float es[Pp];
    __shared__ float red[2];
    int tid = threadIdx.x;
    // att2[b][a] = bias + sum of 8 split-K parts
    {
        int a = tid;  // 512 threads == Aa
        float s = dec_att_b[a];
#pragma unroll
        for (int ks = 0; ks < 8; ks++)
            s += g_part[((size_t)(ks * 32 + b)) * 2560 + a];
        t2s[a] = s;
        ws[a] = full_w[a];
    }
    __syncthreads();
    int warp = tid >> 5, lane = tid & 31;
    float fb = *full_b;

    for (int p = warp; p < Pp; p += 16) {
        const float4* row = (const float4*)(g_att1 + ((size_t)(b * Pp + p)) * Aa);
        float s = 0.f;
#pragma unroll
        for (int a4 = lane; a4 < Aa / 4; a4 += 32) {
            float4 v = row[a4];
            float4 tt = *(const float4*)&t2s[a4 * 4];
            float4 w = *(const float4*)&ws[a4 * 4];
            s += fmaxf(v.x + tt.x, 0.f) * w.x;
            s += fmaxf(v.y + tt.y, 0.f) * w.y;
            s += fmaxf(v.z + tt.z, 0.f) * w.z;
            s += fmaxf(v.w + tt.w, 0.f) * w.w;
        }
#pragma unroll
        for (int o = 16; o; o >>= 1) s += __shfl_down_sync(0xffffffffu, s, o);
        if (lane == 0) es[p] = s + fb;
    }
    __syncthreads();

    if (warp == 0) {
        float mx = -FLT_MAX;
        for (int p = lane; p < Pp; p += 32) mx = fmaxf(mx, es[p]);
#pragma unroll
        for (int o = 16; o; o >>= 1)
            mx = fmaxf(mx, __shfl_xor_sync(0xffffffffu, mx, o));
        float sm = 0.f;
        for (int p = lane; p < Pp; p += 32) sm += expf(es[p] - mx);
#pragma unroll
        for (int o = 16; o; o >>= 1) sm += __shfl_xor_sync(0xffffffffu, sm, o);
        if (lane == 0) { red[0] = mx; red[1] = sm; }
    }
    __syncthreads();
    float mx = red[0], sm = red[1];
    int active = (t < g_declen[b]);
    if (tid < Pp) {
        float al = expf(es[tid] - mx) / sm;
        g_alpha[b * Pp + tid] = al;
        out[OUT_ALPHA + ((size_t)b * Tt + t) * Pp + tid] = active ? al : 0.f;
    }
}

// ---------------- awe: gate reduce+sigmoid, alpha^T @ enc -> x[512:2560] ----
__global__ void awe_kernel(const float* __restrict__ enc,
                           const float* __restrict__ f_beta_b) {
    int b = blockIdx.y;
    __shared__ float al[Pp];
    for (int p = threadIdx.x; p < Pp; p += blockDim.x) al[p] = g_alpha[b * Pp + p];
    __syncthreads();
    int d = blockIdx.x * blockDim.x + threadIdx.x;
    // gate = sigmoid(f_beta_b + sum of 8 parts at column 512+d)
    float gp = f_beta_b[d];
#pragma unroll
    for (int ks = 0; ks < 8; ks++)
        gp += g_part[((size_t)(ks * 32 + b)) * 2560 + 512 + d];
    float gate = sigf(gp);

    int sb = g_sort[b];
    const float* base = enc + (size_t)sb * Pp * Dd + d;
    float s0 = 0.f, s1 = 0.f;
#pragma unroll 2
    for (int p = 0; p < Pp; p += 2) {
        s0 += base[(size_t)p * Dd] * al[p];
        s1 += base[(size_t)(p + 1) * Dd] * al[p + 1];
    }
    g_x[b * 3072 + 512 + d] = (s0 + s1) * gate;
}

// ---------------- LSTM cell: reduce gates (KS=24), update h/c, feed next ---
__global__ void reduce_lstm_cell(const float* __restrict__ lstm_b, int t) {
    int idx = blockIdx.x * blockDim.x + threadIdx.x;  // 32*512
    int b = idx >> 9, j = idx & 511;
    float s[4];
#pragma unroll
    for (int g = 0; g < 4; g++) {
        int n = g * 512 + j;
        float acc = lstm_b[n];
        for (int ks = 0; ks < 24; ks++)
            acc += g_part[((size_t)(ks * 32 + b)) * 2048 + n];
        s[g] = acc;
    }
    float c_old = g_c[idx];
    float c_new = sigf(s[1]) * c_old + sigf(s[0]) * tanhf(s[2]);
    float h_new = sigf(s[3]) * tanhf(c_new);
    g_hall[((size_t)t * Bt + b) * Hh + j] = h_new;
    int active = (t < g_declen[b]);
    float h_keep = active ? h_new : g_h[idx];
    float c_keep = active ? c_new : c_old;
    g_h[idx] = h_keep;
    g_c[idx] = c_keep;
    g_x[b * 3072 + 2560 + j] = h_keep;
    if (t + 1 < Tt)
        g_x[b * 3072 + j] = g_embs[((size_t)b * Tt + (t + 1)) * Ee + j];
}

// ---------------- att1 = enc_sorted @ enc_att_w + b  (6272x512, K=2048) ----
// tile 128x64, BK=16, 256 threads, 8x4 register tile packed into f32x2 pairs
__global__ void att1_gemm(const float* __restrict__ enc,
                          const float* __restrict__ W,
                          const float* __restrict__ bias) {
    __shared__ __align__(16) float As[16][128];
    __shared__ __align__(16) float Bs[16][64];
    int tid = threadIdx.x;
    int bn = blockIdx.y * 64;

    int lm = tid & 127;
    int kq = tid >> 7;            // 0 or 1
    int gm = blockIdx.x * 128 + lm;
    int bb = gm / 196, pp = gm - bb * 196;
    const float* arow = enc + ((size_t)g_sort[bb] * Pp + pp) * Dd;

    int bkk = tid >> 4;           // 0..15
    int bn4 = (tid & 15) * 4;

    int ty = tid >> 4, tx = tid & 15;

    ull accp[4][4];
#pragma unroll
    for (int i = 0; i < 4; i++)
#pragma unroll
        for (int j = 0; j < 4; j++) accp[i][j] = 0ULL;

    for (int k0 = 0; k0 < Dd; k0 += 16) {
        float4 v1 = *(const float4*)(arow + k0 + kq * 4);
        float4 v2 = *(const float4*)(arow + k0 + kq * 4 + 8);
        As[kq * 4 + 0][lm] = v1.x;
        As[kq * 4 + 1][lm] = v1.y;
        As[kq * 4 + 2][lm] = v1.z;
        As[kq * 4 + 3][lm] = v1.w;
        As[kq * 4 + 8][lm] = v2.x;
        As[kq * 4 + 9][lm] = v2.y;
        As[kq * 4 + 10][lm] = v2.z;
        As[kq * 4 + 11][lm] = v2.w;
        *(float4*)&Bs[bkk][bn4] =
            *(const float4*)(W + (size_t)(k0 + bkk) * Aa + bn + bn4);
        __syncthreads();
#pragma unroll
        for (int kk = 0; kk < 16; kk++) {
            const ull* ap = (const ull*)&As[kk][ty * 8];
            float4 bv = *(const float4*)&Bs[kk][tx * 4];
            ull b0 = pk2(bv.x), b1 = pk2(bv.y), b2 = pk2(bv.z), b3 = pk2(bv.w);
            ull a0 = ap[0], a1 = ap[1], a2 = ap[2], a3 = ap[3];
            fm2(accp[0][0], a0, b0); fm2(accp[0][1], a0, b1);
            fm2(accp[0][2], a0, b2); fm2(accp[0][3], a0, b3);
            fm2(accp[1][0], a1, b0); fm2(accp[1][1], a1, b1);
            fm2(accp[1][2], a1, b2); fm2(accp[1][3], a1, b3);
            fm2(accp[2][0], a2, b0); fm2(accp[2][1], a2, b1);
            fm2(accp[2][2], a2, b2); fm2(accp[2][3], a2, b3);
            fm2(accp[3][0], a3, b0); fm2(accp[3][1], a3, b1);
            fm2(accp[3][2], a3, b2); fm2(accp[3][3], a3, b3);
        }
        __syncthreads();
    }
    int rm = blockIdx.x * 128 + ty * 8;
#pragma unroll
    for (int ip = 0; ip < 4; ip++) {
#pragma unroll
        for (int j = 0; j < 4; j++) {
            float2 v = up2(accp[ip][j]);
            float bj = bias[bn + tx * 4 + j];
            g_att1[(size_t)(rm + 2 * ip) * Aa + bn + tx * 4 + j]     = v.x + bj;
            g_att1[(size_t)(rm + 2 * ip + 1) * Aa + bn + tx * 4 + j] = v.y + bj;
        }
    }
}

// ---------------- deferred fc: preds = h_all @ fc_w + b, masked ------------
// M=640 (m = t*32+b), N=10000, K=512. tile 64x64, BK=16, 4x4 micro, f32x2.
__global__ void fc_gemm(const float* __restrict__ fc_w,
                        const float* __restrict__ fc_b,
                        float* __restrict__ out) {
    __shared__ __align__(16) float As[16][64];
    __shared__ __align__(16) float Bs[16][64];
    int tid = threadIdx.x;
    int bm = blockIdx.x * 64;
    int bn = blockIdx.y * 64;

    int lm = tid & 63;
    int kq = tid >> 6;            // 0..3
    const float* arow = g_hall + (size_t)(bm + lm) * Hh;

    int bkk = tid >> 4;
    int bn4 = (tid & 15) * 4;

    int ty = tid >> 4, tx = tid & 15;

    ull accp[2][4];
#pragma unroll
    for (int i = 0; i < 2; i++)
#pragma unroll
        for (int j = 0; j < 4; j++) accp[i][j] = 0ULL;

    for (int k0 = 0; k0 < Hh; k0 += 16) {
        float4 v = *(const float4*)(arow + k0 + kq * 4);
        As[kq * 4 + 0][lm] = v.x;
        As[kq * 4 + 1][lm] = v.y;
        As[kq * 4 + 2][lm] = v.z;
        As[kq * 4 + 3][lm] = v.w;
        int gn = bn + bn4;
        if (gn < Vv) {
            *(float4*)&Bs[bkk][bn4] =
                *(const float4*)(fc_w + (size_t)(k0 + bkk) * Vv + gn);
        } else {
            Bs[bkk][bn4] = 0.f; Bs[bkk][bn4 + 1] = 0.f;
            Bs[bkk][bn4 + 2] = 0.f; Bs[bkk][bn4 + 3] = 0.f;
        }
        __syncthreads();
#pragma unroll
        for (int kk = 0; kk < 16; kk++) {
            const ull* ap = (const ull*)&As[kk][ty * 4];
            float4 bv = *(const float4*)&Bs[kk][tx * 4];
            ull b0 = pk2(bv.x), b1 = pk2(bv.y), b2 = pk2(bv.z), b3 = pk2(bv.w);
            ull a0 = ap[0], a1 = ap[1];
            fm2(accp[0][0], a0, b0); fm2(accp[0][1], a0, b1);
            fm2(accp[0][2], a0, b2); fm2(accp[0][3], a0, b3);
            fm2(accp[1][0], a1, b0); fm2(accp[1][1], a1, b1);
            fm2(accp[1][2], a1, b2); fm2(accp[1][3], a1, b3);
        }
        __syncthreads();
    }
    int gn0 = bn + tx * 4;
    if (gn0 >= Vv) return;
#pragma unroll
    for (int ip = 0; ip < 2; ip++) {
#pragma unroll
        for (int rr = 0; rr < 2; rr++) {
            int m = bm + ty * 4 + 2 * ip + rr;   // m = t*32 + b
            int t = m >> 5, b = m & 31;
            int active = (t < g_declen[b]);
            size_t obase = OUT_PRED + ((size_t)b * Tt + t) * Vv + gn0;
#pragma unroll
            for (int j = 0; j < 4; j++) {
                float2 v = up2(accp[ip][j]);
                float val = rr == 0 ? v.x : v.y;
                out[obase + j] = active ? (val + fc_b[gn0 + j]) : 0.f;
            }
        }
    }
}

// ---------------- launch ----------------------------------------------------
extern "C" void kernel_launch(void* const* d_in, const int* in_sizes, int n_in,
                              void* d_out, int out_size) {
    const float* enc        = (const float*)d_in[0];
    const int*   caps_in    = (const int*)d_in[1];
    const int*   caplen     = (const int*)d_in[2];
    const float* enc_att_w  = (const float*)d_in[3];
    const float* enc_att_b  = (const float*)d_in[4];
    const float* dec_att_w  = (const float*)d_in[5];
    const float* dec_att_b  = (const float*)d_in[6];
    const float* full_att_w = (const float*)d_in[7];
    const float* full_att_b = (const float*)d_in[8];
    const float* emb        = (const float*)d_in[9];
    const float* init_h_w   = (const float*)d_in[10];
    const float* init_h_b   = (const float*)d_in[11];
    const float* init_c_w   = (const float*)d_in[12];
    const float* init_c_b   = (const float*)d_in[13];
    const float* f_beta_w   = (const float*)d_in[14];
    const float* f_beta_b   = (const float*)d_in[15];
    const float* lstm_w_ih  = (const float*)d_in[16];
    const float* lstm_w_hh  = (const float*)d_in[17];
    const float* lstm_b     = (const float*)d_in[18];
    const float* fc_w       = (const float*)d_in[19];
    const float* fc_b       = (const float*)d_in[20];
    float* out = (float*)d_out;
    const int BIG = 1 << 30;

    setup_kernel<<<1, 32>>>(caplen, caps_in, out);
    emb_gather<<<1280, 256>>>(emb);
    mean_kernel<<<32, 256>>>(enc);

    // fused [h0|c0] = mean @ [init_h_w|init_c_w]  (K=2048, N=1024, KS=16)
    skinny2<<<dim3(4, 16), 256>>>(init_h_w, 512, init_c_w, 512, 512,
                                  init_h_w, 512, BIG, 2048, 1024, 128, 2);
    reduce_init_hc<<<128, 256>>>(init_h_b, init_c_b);

    // att1 = enc_sorted @ enc_att_w + b   (6272 x 512, K=2048)
    att1_gemm<<<dim3(49, 8), 256>>>(enc, enc_att_w, enc_att_b);

    for (int t = 0; t < Tt; t++) {
        // [att2 | gate_pre] = h @ [dec_att_w | f_beta_w]  (K=512, N=2560, KS=8)
        skinny2<<<dim3(10, 8), 256>>>(dec_att_w, 512, f_beta_w, 2048, 512,
                                      dec_att_w, 512, BIG, 512, 2560, 64, 0);
        // att2 reduce + e + softmax + alpha (masked write)
        attn_kernel<<<32, 512>>>(dec_att_b, full_att_w, full_att_b, out, t);
        // gate reduce+sigmoid + awe into x[512:2560]
        awe_kernel<<<dim3(8, 32), 256>>>(enc, f_beta_b);
        // gates = x @ [w_ih; w_hh]   (K=3072, N=2048, KS=24, k-split at 2560)
        skinny2<<<dim3(8, 24), 256>>>(lstm_w_ih, 2048, lstm_w_ih, 2048, 2048,
                                      lstm_w_hh, 2048, 2560, 3072, 2048, 128, 1);
        reduce_lstm_cell<<<64, 256>>>(lstm_b, t);
    }

    // preds = h_all @ fc_w + b (masked), one big GEMM after the loop
    fc_gemm<<<dim3(10, 157), 256>>>(fc_w, fc_b, out);
}

// round 4
// speedup vs baseline: 3.8859x; 1.1889x over previous
#include <cuda_runtime.h>
#include <math.h>
#include <float.h>

#define Bt 32
#define Pp 196
#define Dd 2048
#define Aa 512
#define Ee 512
#define Hh 512
#define Vv 10000
#define Ll 21
#define Tt 20

// output layout (float32, concatenated in return-tuple order)
#define OUT_PRED   0
#define OUT_CAPS   6400000
#define OUT_DECLEN 6400672
#define OUT_ALPHA  6400704
#define OUT_SORT   6526144

typedef unsigned long long ull;

// ---------------- packed f32x2 helpers --------------------------------------
__device__ __forceinline__ ull pk2(float x) {
    ull r; asm("mov.b64 %0, {%1, %1};" : "=l"(r) : "f"(x)); return r;
}
__device__ __forceinline__ void fm2(ull& d, ull a, ull b) {
    asm("fma.rn.f32x2 %0, %1, %2, %0;" : "+l"(d) : "l"(a), "l"(b));
}
__device__ __forceinline__ float2 up2(ull v) {
    float2 r; asm("mov.b64 {%0, %1}, %2;" : "=f"(r.x), "=f"(r.y) : "l"(v)); return r;
}

// ---------------- scratch (device globals; no runtime allocation) ----------
__device__ int   g_sort[Bt];
__device__ int   g_declen[Bt];
__device__ int   g_caps[Bt * Ll];
__device__ float g_mean[Bt * Dd];
__device__ float g_h[Bt * Hh];
__device__ float g_c[Bt * Hh];
__device__ float g_att1[Bt * Pp * Aa];     // 12.8 MB
__device__ float g_escore[Bt * Pp];
__device__ float g_x[Bt * 3072];           // [emb | awe | h]
__device__ float g_embs[Bt * Tt * Ee];     // all embeddings, gathered once
__device__ float g_hall[Tt * Bt * Hh];     // h_new per step (for deferred fc)
__device__ float g_part[3200000];          // split-K partial buffer
__device__ unsigned g_bar;                 // grid barrier counter

__device__ __forceinline__ float sigf(float x) { return 1.0f / (1.0f + expf(-x)); }

// ---------------- grid barrier (all 256 blocks co-resident) ----------------
__device__ __forceinline__ void gsync(unsigned target) {
    __syncthreads();
    if (threadIdx.x == 0) {
        __threadfence();                 // flush + order writes (CCTL.IVALL)
        atomicAdd(&g_bar, 1u);
        while (*((volatile unsigned*)&g_bar) < target) __nanosleep(40);
        __threadfence();                 // invalidate L1 before consuming
    }
    __syncthreads();
}

__global__ void reset_bar() { g_bar = 0u; }

// ---------------- setup: stable descending argsort + caps/declen out -------
__global__ void setup_kernel(const int* __restrict__ caplen,
                             const int* __restrict__ caps_in,
                             float* __restrict__ out) {
    __shared__ int len[Bt];
    int b = threadIdx.x;
    if (b < Bt) len[b] = caplen[b];
    __syncthreads();
    if (b < Bt) {
        int myl = len[b];
        int rank = 0;
        for (int j = 0; j < Bt; j++) {
            int lj = len[j];
            if (lj > myl || (lj == myl && j < b)) rank++;
        }
        g_sort[rank] = b;
    }
    __syncthreads();
    if (b < Bt) {
        int sb = g_sort[b];
        int dl = len[sb] - 1;
        g_declen[b] = dl;
        out[OUT_SORT + b]   = (float)sb;
        out[OUT_DECLEN + b] = (float)dl;
        for (int l = 0; l < Ll; l++) {
            int tok = caps_in[sb * Ll + l];
            g_caps[b * Ll + l] = tok;
            out[OUT_CAPS + b * Ll + l] = (float)tok;
        }
    }
}

// ---------------- gather ALL embeddings once; seed x emb part for t=0 ------
__global__ void emb_gather(const float* __restrict__ emb) {
    int i = blockIdx.x * blockDim.x + threadIdx.x;   // 32*20*512
    if (i >= Bt * Tt * Ee) return;
    int b = i / (Tt * Ee);
    int r = i - b * (Tt * Ee);
    int t = r >> 9;
    int j = r & 511;
    int tok = g_caps[b * Ll + t];
    float v = emb[(size_t)tok * Ee + j];
    g_embs[i] = v;
    if (t == 0) g_x[b * 3072 + j] = v;
}

// ---------------- mean over P of sorted encoder rows (wide) ----------------
__global__ void mean_kernel(const float* __restrict__ enc) {
    int b = blockIdx.y;
    int d = blockIdx.x * 256 + threadIdx.x;
    int sb = g_sort[b];
    const float* base = enc + (size_t)sb * Pp * Dd + d;
    float s0 = 0.f, s1 = 0.f;
    for (int p = 0; p < Pp; p += 2) {
        s0 += base[(size_t)p * Dd];
        s1 += base[(size_t)(p + 1) * Dd];
    }
    g_mean[b * Dd + d] = (s0 + s1) / 196.0f;
}

// ---------------- skinny split-K body (f32x2, 32 rows) ---------------------
__device__ __forceinline__ void skinny_body(const float* xs, const float* W,
                                            int st, int kPer,
                                            float* prow, int N) {
    ull acc[16];
#pragma unroll
    for (int i = 0; i < 16; i++) acc[i] = 0ULL;
#pragma unroll 1
    for (int kk = 0; kk < kPer; kk += 4) {
        float w0 = W[(size_t)(kk + 0) * st];
        float w1 = W[(size_t)(kk + 1) * st];
        float w2 = W[(size_t)(kk + 2) * st];
        float w3 = W[(size_t)(kk + 3) * st];
        const ull* x0 = (const ull*)(xs + (kk + 0) * 34);
        const ull* x1 = (const ull*)(xs + (kk + 1) * 34);
        const ull* x2 = (const ull*)(xs + (kk + 2) * 34);
        const ull* x3 = (const ull*)(xs + (kk + 3) * 34);
        ull wp;
        wp = pk2(w0);
#pragma unroll
        for (int i = 0; i < 16; i++) fm2(acc[i], x0[i], wp);
        wp = pk2(w1);
#pragma unroll
        for (int i = 0; i < 16; i++) fm2(acc[i], x1[i], wp);
        wp = pk2(w2);
#pragma unroll
        for (int i = 0; i < 16; i++) fm2(acc[i], x2[i], wp);
        wp = pk2(w3);
#pragma unroll
        for (int i = 0; i < 16; i++) fm2(acc[i], x3[i], wp);
    }
#pragma unroll
    for (int mp = 0; mp < 16; mp++) {
        float2 v = up2(acc[mp]);
        prow[(size_t)(2 * mp) * N]     = v.x;
        prow[(size_t)(2 * mp + 1) * N] = v.y;
    }
}

// ---------------- init skinny: [h0|c0] = mean @ [Wh|Wc], KS=32 -------------
__global__ void init_part(const float* __restrict__ Wh,
                          const float* __restrict__ Wc) {
    __shared__ __align__(16) float xs[64 * 34];
    int kBeg = blockIdx.y * 64;
    for (int i = threadIdx.x; i < 32 * 64; i += 256) {
        int m = i >> 6, kk = i & 63;
        xs[kk * 34 + m] = g_mean[m * 2048 + kBeg + kk];
    }
    __syncthreads();
    int n = blockIdx.x * 256 + threadIdx.x;    // < 1024
    const float* W = (n < 512) ? (Wh + (size_t)kBeg * 512 + n)
                               : (Wc + (size_t)kBeg * 512 + (n - 512));
    skinny_body(xs, W, 512, 64,
                g_part + (size_t)(blockIdx.y * 32) * 1024 + n, 1024);
}

__global__ void reduce_init_hc(const float* __restrict__ init_h_b,
                               const float* __restrict__ init_c_b) {
    int idx = blockIdx.x * blockDim.x + threadIdx.x;   // 32*1024
    if (idx >= 32 * 1024) return;
    int m = idx >> 10, n = idx & 1023;
    float s = 0.f;
#pragma unroll 8
    for (int ks = 0; ks < 32; ks++) s += g_part[((size_t)(ks * 32 + m)) * 1024 + n];
    if (n < 512) {
        float v = s + init_h_b[n];
        g_h[m * 512 + n] = v;
        g_x[m * 3072 + 2560 + n] = v;
    } else {
        g_c[m * 512 + (n - 512)] = s + init_c_b[n - 512];
    }
}

// ---------------- att1 = enc_sorted @ enc_att_w + b  (6272x512, K=2048) ----
// tile 128x64, BK=16, 256 threads, 8x4 register tile packed into f32x2 pairs
__global__ void att1_gemm(const float* __restrict__ enc,
                          const float* __restrict__ W,
                          const float* __restrict__ bias) {
    __shared__ __align__(16) float As[16][128];
    __shared__ __align__(16) float Bs[16][64];
    int tid = threadIdx.x;
    int bn = blockIdx.y * 64;

    int lm = tid & 127;
    int kq = tid >> 7;            // 0 or 1
    int gm = blockIdx.x * 128 + lm;
    int bb = gm / 196, pp = gm - bb * 196;
    const float* arow = enc + ((size_t)g_sort[bb] * Pp + pp) * Dd;

    int bkk = tid >> 4;           // 0..15
    int bn4 = (tid & 15) * 4;

    int ty = tid >> 4, tx = tid & 15;

    ull accp[4][4];
#pragma unroll
    for (int i = 0; i < 4; i++)
#pragma unroll
        for (int j = 0; j < 4; j++) accp[i][j] = 0ULL;

    for (int k0 = 0; k0 < Dd; k0 += 16) {
        float4 v1 = *(const float4*)(arow + k0 + kq * 4);
        float4 v2 = *(const float4*)(arow + k0 + kq * 4 + 8);
        As[kq * 4 + 0][lm] = v1.x;
        As[kq * 4 + 1][lm] = v1.y;
        As[kq * 4 + 2][lm] = v1.z;
        As[kq * 4 + 3][lm] = v1.w;
        As[kq * 4 + 8][lm] = v2.x;
        As[kq * 4 + 9][lm] = v2.y;
        As[kq * 4 + 10][lm] = v2.z;
        As[kq * 4 + 11][lm] = v2.w;
        *(float4*)&Bs[bkk][bn4] =
            *(const float4*)(W + (size_t)(k0 + bkk) * Aa + bn + bn4);
        __syncthreads();
#pragma unroll
        for (int kk = 0; kk < 16; kk++) {
            const ull* ap = (const ull*)&As[kk][ty * 8];
            float4 bv = *(const float4*)&Bs[kk][tx * 4];
            ull b0 = pk2(bv.x), b1 = pk2(bv.y), b2 = pk2(bv.z), b3 = pk2(bv.w);
            ull a0 = ap[0], a1 = ap[1], a2 = ap[2], a3 = ap[3];
            fm2(accp[0][0], a0, b0); fm2(accp[0][1], a0, b1);
            fm2(accp[0][2], a0, b2); fm2(accp[0][3], a0, b3);
            fm2(accp[1][0], a1, b0); fm2(accp[1][1], a1, b1);
            fm2(accp[1][2], a1, b2); fm2(accp[1][3], a1, b3);
            fm2(accp[2][0], a2, b0); fm2(accp[2][1], a2, b1);
            fm2(accp[2][2], a2, b2); fm2(accp[2][3], a2, b3);
            fm2(accp[3][0], a3, b0); fm2(accp[3][1], a3, b1);
            fm2(accp[3][2], a3, b2); fm2(accp[3][3], a3, b3);
        }
        __syncthreads();
    }
    int rm = blockIdx.x * 128 + ty * 8;
#pragma unroll
    for (int ip = 0; ip < 4; ip++) {
#pragma unroll
        for (int j = 0; j < 4; j++) {
            float2 v = up2(accp[ip][j]);
            float bj = bias[bn + tx * 4 + j];
            g_att1[(size_t)(rm + 2 * ip) * Aa + bn + tx * 4 + j]     = v.x + bj;
            g_att1[(size_t)(rm + 2 * ip + 1) * Aa + bn + tx * 4 + j] = v.y + bj;
        }
    }
}

// ---------------- persistent kernel: entire 20-step decode loop ------------
__global__ void __launch_bounds__(256, 2) loop_kernel(
    const float* __restrict__ enc,
    const float* __restrict__ dec_att_w, const float* __restrict__ dec_att_b,
    const float* __restrict__ f_beta_w,  const float* __restrict__ f_beta_b,
    const float* __restrict__ full_w,    const float* __restrict__ full_b,
    const float* __restrict__ lstm_w_ih, const float* __restrict__ lstm_w_hh,
    const float* __restrict__ lstm_b,
    float* __restrict__ out)
{
    __shared__ __align__(16) float sb[2304];
    __shared__ float red[16];
    const int bid = blockIdx.x, tid = threadIdx.x;
    const int warp = tid >> 5, lane = tid & 31;
    const unsigned G = 256;
    unsigned tgt = 0;

    for (int t = 0; t < Tt; t++) {
        // ---- P1: [att2|gate] parts = h @ [dec_att_w | f_beta_w], KS=16 ----
        if (bid < 160) {
            int nx = bid % 10, ky = bid / 10;
            int kBeg = ky * 32;
            for (int i = tid; i < 32 * 32; i += 256) {
                int m = i >> 5, kk = i & 31;
                sb[kk * 34 + m] = g_h[m * 512 + kBeg + kk];
            }
            __syncthreads();
            int n = nx * 256 + tid;
            const float* W; int st;
            if (n < 512) { W = dec_att_w + (size_t)kBeg * 512 + n; st = 512; }
            else         { W = f_beta_w + (size_t)kBeg * 2048 + (n - 512); st = 2048; }
            skinny_body(sb, W, st, 32,
                        g_part + (size_t)(ky * 32) * 2560 + n, 2560);
        }
        gsync(tgt += G);

        // ---- P2: attention scores -> g_escore (256 blocks: b x pchunk) ----
        {
            int b = bid >> 3, pc = bid & 7;
#pragma unroll
            for (int rep = 0; rep < 2; rep++) {
                int aa = rep * 256 + tid;
                float s = dec_att_b[aa];
#pragma unroll
                for (int ks = 0; ks < 16; ks++)
                    s += g_part[(size_t)(ks * 32 + b) * 2560 + aa];
                sb[aa] = s;               // t2s in [0,512)
                sb[512 + aa] = full_w[aa];
            }
            __syncthreads();
            float fb = *full_b;
            int pbeg = pc * 25;
            int pend = min(196, pbeg + 25);
            for (int p = pbeg + warp; p < pend; p += 8) {
                const float4* row = (const float4*)(g_att1 + (size_t)(b * 196 + p) * 512);
                float s = 0.f;
#pragma unroll
                for (int a4 = lane; a4 < 128; a4 += 32) {
                    float4 v = row[a4];
                    float4 tt = *(const float4*)&sb[a4 * 4];
                    float4 w = *(const float4*)&sb[512 + a4 * 4];
                    s += fmaxf(v.x + tt.x, 0.f) * w.x;
                    s += fmaxf(v.y + tt.y, 0.f) * w.y;
                    s += fmaxf(v.z + tt.z, 0.f) * w.z;
                    s += fmaxf(v.w + tt.w, 0.f) * w.w;
                }
#pragma unroll
                for (int o = 16; o; o >>= 1) s += __shfl_down_sync(0xffffffffu, s, o);
                if (lane == 0) g_escore[b * 196 + p] = s + fb;
            }
        }
        gsync(tgt += G);

        // ---- P3: softmax (redundant per block) + gate + awe -> x ----------
        {
            int b = bid >> 3, dc = bid & 7;
            int sbt = g_sort[b];
            float e = (tid < 196) ? g_escore[b * 196 + tid] : -FLT_MAX;
            float m = e;
#pragma unroll
            for (int o = 16; o; o >>= 1)
                m = fmaxf(m, __shfl_xor_sync(0xffffffffu, m, o));
            if (lane == 0) red[warp] = m;
            __syncthreads();
            if (tid == 0) {
                float mm = red[0];
#pragma unroll
                for (int i = 1; i < 8; i++) mm = fmaxf(mm, red[i]);
                red[8] = mm;
            }
            __syncthreads();
            float mx = red[8];
            float ex = (tid < 196) ? expf(e - mx) : 0.f;
            float ss = ex;
#pragma unroll
            for (int o = 16; o; o >>= 1) ss += __shfl_xor_sync(0xffffffffu, ss, o);
            if (lane == 0) red[warp] = ss;
            __syncthreads();
            if (tid == 0) {
                float s2 = 0.f;
#pragma unroll
                for (int i = 0; i < 8; i++) s2 += red[i];
                red[9] = s2;
            }
            __syncthreads();
            float inv = 1.f / red[9];
            if (tid < 196) sb[tid] = ex * inv;   // alpha
            __syncthreads();
            int active = (t < g_declen[b]);
            if (dc == 0 && tid < 196)
                out[OUT_ALPHA + (size_t)(b * Tt + t) * 196 + tid] =
                    active ? sb[tid] : 0.f;
            int d = dc * 256 + tid;
            float gp = f_beta_b[d];
#pragma unroll
            for (int ks = 0; ks < 16; ks++)
                gp += g_part[(size_t)(ks * 32 + b) * 2560 + 512 + d];
            float gate = sigf(gp);
            const float* base = enc + (size_t)sbt * Pp * Dd + d;
            float s0 = 0.f, s1 = 0.f;
#pragma unroll 2
            for (int p = 0; p < 196; p += 2) {
                s0 += base[(size_t)p * Dd] * sb[p];
                s1 += base[(size_t)(p + 1) * Dd] * sb[p + 1];
            }
            g_x[b * 3072 + 512 + d] = (s0 + s1) * gate;
        }
        gsync(tgt += G);

        // ---- P4: lstm gates parts = x @ [w_ih;w_hh], KS=48 (384 vb) -------
        for (int vb = bid; vb < 384; vb += 256) {
            int nx = vb & 7, ky = vb >> 3;
            int kBeg = ky * 64;
            __syncthreads();
            for (int i = tid; i < 32 * 64; i += 256) {
                int m = i >> 6, kk = i & 63;
                sb[kk * 34 + m] = g_x[m * 3072 + kBeg + kk];
            }
            __syncthreads();
            int n = nx * 256 + tid;
            const float* W = (kBeg < 2560)
                ? (lstm_w_ih + (size_t)kBeg * 2048 + n)
                : (lstm_w_hh + (size_t)(kBeg - 2560) * 2048 + n);
            skinny_body(sb, W, 2048, 64,
                        g_part + (size_t)(ky * 32) * 2048 + n, 2048);
        }
        gsync(tgt += G);

        // ---- P5: LSTM cell (64 blocks) ------------------------------------
        if (bid < 64) {
            int idx = bid * 256 + tid;
            int b = idx >> 9, j = idx & 511;
            float s[4];
#pragma unroll
            for (int g = 0; g < 4; g++) {
                int n = g * 512 + j;
                float acc = lstm_b[n];
#pragma unroll 8
                for (int ks = 0; ks < 48; ks++)
                    acc += g_part[(size_t)(ks * 32 + b) * 2048 + n];
                s[g] = acc;
            }
            float c_old = g_c[idx];
            float c_new = sigf(s[1]) * c_old + sigf(s[0]) * tanhf(s[2]);
            float h_new = sigf(s[3]) * tanhf(c_new);
            g_hall[((size_t)t * Bt + b) * Hh + j] = h_new;
            int active = (t < g_declen[b]);
            float h_keep = active ? h_new : g_h[idx];
            float c_keep = active ? c_new : c_old;
            g_h[idx] = h_keep;
            g_c[idx] = c_keep;
            g_x[b * 3072 + 2560 + j] = h_keep;
            if (t + 1 < Tt)
                g_x[b * 3072 + j] = g_embs[((size_t)b * Tt + (t + 1)) * Ee + j];
        }
        gsync(tgt += G);
    }
}

// ---------------- deferred fc: preds = h_all @ fc_w + b, masked ------------
__global__ void fc_gemm(const float* __restrict__ fc_w,
                        const float* __restrict__ fc_b,
                        float* __restrict__ out) {
    __shared__ __align__(16) float As[16][64];
    __shared__ __align__(16) float Bs[16][64];
    int tid = threadIdx.x;
    int bm = blockIdx.x * 64;
    int bn = blockIdx.y * 64;

    int lm = tid & 63;
    int kq = tid >> 6;            // 0..3
    const float* arow = g_hall + (size_t)(bm + lm) * Hh;

    int bkk = tid >> 4;
    int bn4 = (tid & 15) * 4;

    int ty = tid >> 4, tx = tid & 15;

    ull accp[2][4];
#pragma unroll
    for (int i = 0; i < 2; i++)
#pragma unroll
        for (int j = 0; j < 4; j++) accp[i][j] = 0ULL;

    for (int k0 = 0; k0 < Hh; k0 += 16) {
        float4 v = *(const float4*)(arow + k0 + kq * 4);
        As[kq * 4 + 0][lm] = v.x;
        As[kq * 4 + 1][lm] = v.y;
        As[kq * 4 + 2][lm] = v.z;
        As[kq * 4 + 3][lm] = v.w;
        int gn = bn + bn4;
        if (gn < Vv) {
            *(float4*)&Bs[bkk][bn4] =
                *(const float4*)(fc_w + (size_t)(k0 + bkk) * Vv + gn);
        } else {
            Bs[bkk][bn4] = 0.f; Bs[bkk][bn4 + 1] = 0.f;
            Bs[bkk][bn4 + 2] = 0.f; Bs[bkk][bn4 + 3] = 0.f;
        }
        __syncthreads();
#pragma unroll
        for (int kk = 0; kk < 16; kk++) {
            const ull* ap = (const ull*)&As[kk][ty * 4];
            float4 bv = *(const float4*)&Bs[kk][tx * 4];
            ull b0 = pk2(bv.x), b1 = pk2(bv.y), b2 = pk2(bv.z), b3 = pk2(bv.w);
            ull a0 = ap[0], a1 = ap[1];
            fm2(accp[0][0], a0, b0); fm2(accp[0][1], a0, b1);
            fm2(accp[0][2], a0, b2); fm2(accp[0][3], a0, b3);
            fm2(accp[1][0], a1, b0); fm2(accp[1][1], a1, b1);
            fm2(accp[1][2], a1, b2); fm2(accp[1][3], a1, b3);
        }
        __syncthreads();
    }
    int gn0 = bn + tx * 4;
    if (gn0 >= Vv) return;
#pragma unroll
    for (int ip = 0; ip < 2; ip++) {
#pragma unroll
        for (int rr = 0; rr < 2; rr++) {
            int m = bm + ty * 4 + 2 * ip + rr;   // m = t*32 + b
            int t = m >> 5, b = m & 31;
            int active = (t < g_declen[b]);
            size_t obase = OUT_PRED + ((size_t)b * Tt + t) * Vv + gn0;
#pragma unroll
            for (int j = 0; j < 4; j++) {
                float2 v = up2(accp[ip][j]);
                float val = rr == 0 ? v.x : v.y;
                out[obase + j] = active ? (val + fc_b[gn0 + j]) : 0.f;
            }
        }
    }
}

// ---------------- launch ----------------------------------------------------
extern "C" void kernel_launch(void* const* d_in, const int* in_sizes, int n_in,
                              void* d_out, int out_size) {
    const float* enc        = (const float*)d_in[0];
    const int*   caps_in    = (const int*)d_in[1];
    const int*   caplen     = (const int*)d_in[2];
    const float* enc_att_w  = (const float*)d_in[3];
    const float* enc_att_b  = (const float*)d_in[4];
    const float* dec_att_w  = (const float*)d_in[5];
    const float* dec_att_b  = (const float*)d_in[6];
    const float* full_att_w = (const float*)d_in[7];
    const float* full_att_b = (const float*)d_in[8];
    const float* emb        = (const float*)d_in[9];
    const float* init_h_w   = (const float*)d_in[10];
    const float* init_h_b   = (const float*)d_in[11];
    const float* init_c_w   = (const float*)d_in[12];
    const float* init_c_b   = (const float*)d_in[13];
    const float* f_beta_w   = (const float*)d_in[14];
    const float* f_beta_b   = (const float*)d_in[15];
    const float* lstm_w_ih  = (const float*)d_in[16];
    const float* lstm_w_hh  = (const float*)d_in[17];
    const float* lstm_b     = (const float*)d_in[18];
    const float* fc_w       = (const float*)d_in[19];
    const float* fc_b       = (const float*)d_in[20];
    float* out = (float*)d_out;

    setup_kernel<<<1, 32>>>(caplen, caps_in, out);
    emb_gather<<<1280, 256>>>(emb);
    mean_kernel<<<dim3(8, 32), 256>>>(enc);

    // fused [h0|c0] = mean @ [init_h_w|init_c_w]  (K=2048, N=1024, KS=32)
    init_part<<<dim3(4, 32), 256>>>(init_h_w, init_c_w);
    reduce_init_hc<<<128, 256>>>(init_h_b, init_c_b);

    // att1 = enc_sorted @ enc_att_w + b   (6272 x 512, K=2048)
    att1_gemm<<<dim3(49, 8), 256>>>(enc, enc_att_w, enc_att_b);

    // whole 20-step decode loop as one persistent kernel
    reset_bar<<<1, 1>>>();
    loop_kernel<<<256, 256>>>(enc,
                              dec_att_w, dec_att_b,
                              f_beta_w, f_beta_b,
                              full_att_w, full_att_b,
                              lstm_w_ih, lstm_w_hh, lstm_b,
                              out);

    // preds = h_all @ fc_w + b (masked), one big GEMM after the loop
    fc_gemm<<<dim3(10, 157), 256>>>(fc_w, fc_b, out);
}

// round 5
// speedup vs baseline: 3.9407x; 1.0141x over previous
#include <cuda_runtime.h>
#include <math.h>
#include <float.h>

#define Bt 32
#define Pp 196
#define Dd 2048
#define Aa 512
#define Ee 512
#define Hh 512
#define Vv 10000
#define Ll 21
#define Tt 20

// output layout (float32, concatenated in return-tuple order)
#define OUT_PRED   0
#define OUT_CAPS   6400000
#define OUT_DECLEN 6400672
#define OUT_ALPHA  6400704
#define OUT_SORT   6526144

typedef unsigned long long ull;

// ---------------- packed f32x2 helpers --------------------------------------
__device__ __forceinline__ ull pk2(float x) {
    ull r; asm("mov.b64 %0, {%1, %1};" : "=l"(r) : "f"(x)); return r;
}
__device__ __forceinline__ void fm2(ull& d, ull a, ull b) {
    asm("fma.rn.f32x2 %0, %1, %2, %0;" : "+l"(d) : "l"(a), "l"(b));
}
__device__ __forceinline__ float2 up2(ull v) {
    float2 r; asm("mov.b64 {%0, %1}, %2;" : "=f"(r.x), "=f"(r.y) : "l"(v)); return r;
}

// ---------------- tf32 mma helpers ------------------------------------------
__device__ __forceinline__ unsigned tf32of(float x) {
    unsigned r; asm("cvt.rna.tf32.f32 %0, %1;" : "=r"(r) : "f"(x)); return r;
}
__device__ __forceinline__ void mma_tf32(float* c, unsigned a0, unsigned a1,
                                         unsigned a2, unsigned a3,
                                         unsigned b0, unsigned b1) {
    asm("mma.sync.aligned.m16n8k8.row.col.f32.tf32.tf32.f32 "
        "{%0,%1,%2,%3}, {%4,%5,%6,%7}, {%8,%9}, {%0,%1,%2,%3};"
        : "+f"(c[0]), "+f"(c[1]), "+f"(c[2]), "+f"(c[3])
        : "r"(a0), "r"(a1), "r"(a2), "r"(a3), "r"(b0), "r"(b1));
}

// ---------------- scratch (device globals; no runtime allocation) ----------
__device__ int   g_sort[Bt];
__device__ int   g_declen[Bt];
__device__ int   g_caps[Bt * Ll];
__device__ float g_mean[Bt * Dd];
__device__ float g_h[Bt * Hh];
__device__ float g_c[Bt * Hh];
__device__ float g_att1[Bt * Pp * Aa];     // 12.8 MB
__device__ float g_escore[Bt * Pp];
__device__ float g_x[Bt * 3072];           // [emb | awe | h]
__device__ float g_embs[Bt * Tt * Ee];     // all embeddings, gathered once
__device__ float g_hall[Tt * Bt * Hh];     // h_new per step (for deferred fc)
__device__ float g_part[3200000];          // split-K partial buffer
__device__ unsigned g_bar;                 // grid barrier counter

__device__ __forceinline__ float sigf(float x) { return 1.0f / (1.0f + expf(-x)); }

// ---------------- grid barrier (all 256 blocks co-resident) ----------------
__device__ __forceinline__ void gsync(unsigned target) {
    __syncthreads();
    if (threadIdx.x == 0) {
        __threadfence();
        atomicAdd(&g_bar, 1u);
        while (*((volatile unsigned*)&g_bar) < target) __nanosleep(40);
        __threadfence();
    }
    __syncthreads();
}

__global__ void reset_bar() { g_bar = 0u; }

// ---------------- setup: stable descending argsort + caps/declen out -------
__global__ void setup_kernel(const int* __restrict__ caplen,
                             const int* __restrict__ caps_in,
                             float* __restrict__ out) {
    __shared__ int len[Bt];
    int b = threadIdx.x;
    if (b < Bt) len[b] = caplen[b];
    __syncthreads();
    if (b < Bt) {
        int myl = len[b];
        int rank = 0;
        for (int j = 0; j < Bt; j++) {
            int lj = len[j];
            if (lj > myl || (lj == myl && j < b)) rank++;
        }
        g_sort[rank] = b;
    }
    __syncthreads();
    if (b < Bt) {
        int sb = g_sort[b];
        int dl = len[sb] - 1;
        g_declen[b] = dl;
        out[OUT_SORT + b]   = (float)sb;
        out[OUT_DECLEN + b] = (float)dl;
        for (int l = 0; l < Ll; l++) {
            int tok = caps_in[sb * Ll + l];
            g_caps[b * Ll + l] = tok;
            out[OUT_CAPS + b * Ll + l] = (float)tok;
        }
    }
}

// ---------------- gather ALL embeddings once; seed x emb part for t=0 ------
__global__ void emb_gather(const float* __restrict__ emb) {
    int i = blockIdx.x * blockDim.x + threadIdx.x;   // 32*20*512
    if (i >= Bt * Tt * Ee) return;
    int b = i / (Tt * Ee);
    int r = i - b * (Tt * Ee);
    int t = r >> 9;
    int j = r & 511;
    int tok = g_caps[b * Ll + t];
    float v = emb[(size_t)tok * Ee + j];
    g_embs[i] = v;
    if (t == 0) g_x[b * 3072 + j] = v;
}

// ---------------- mean over P of sorted encoder rows (wide) ----------------
__global__ void mean_kernel(const float* __restrict__ enc) {
    int b = blockIdx.y;
    int d = blockIdx.x * 256 + threadIdx.x;
    int sb = g_sort[b];
    const float* base = enc + (size_t)sb * Pp * Dd + d;
    float s0 = 0.f, s1 = 0.f;
    for (int p = 0; p < Pp; p += 2) {
        s0 += base[(size_t)p * Dd];
        s1 += base[(size_t)(p + 1) * Dd];
    }
    g_mean[b * Dd + d] = (s0 + s1) / 196.0f;
}

// ---------------- skinny split-K body (f32x2, 32 rows) ---------------------
__device__ __forceinline__ void skinny_body(const float* xs, const float* W,
                                            int st, int kPer,
                                            float* prow, int N) {
    ull acc[16];
#pragma unroll
    for (int i = 0; i < 16; i++) acc[i] = 0ULL;
#pragma unroll 1
    for (int kk = 0; kk < kPer; kk += 4) {
        float w0 = W[(size_t)(kk + 0) * st];
        float w1 = W[(size_t)(kk + 1) * st];
        float w2 = W[(size_t)(kk + 2) * st];
        float w3 = W[(size_t)(kk + 3) * st];
        const ull* x0 = (const ull*)(xs + (kk + 0) * 34);
        const ull* x1 = (const ull*)(xs + (kk + 1) * 34);
        const ull* x2 = (const ull*)(xs + (kk + 2) * 34);
        const ull* x3 = (const ull*)(xs + (kk + 3) * 34);
        ull wp;
        wp = pk2(w0);
#pragma unroll
        for (int i = 0; i < 16; i++) fm2(acc[i], x0[i], wp);
        wp = pk2(w1);
#pragma unroll
        for (int i = 0; i < 16; i++) fm2(acc[i], x1[i], wp);
        wp = pk2(w2);
#pragma unroll
        for (int i = 0; i < 16; i++) fm2(acc[i], x2[i], wp);
        wp = pk2(w3);
#pragma unroll
        for (int i = 0; i < 16; i++) fm2(acc[i], x3[i], wp);
    }
#pragma unroll
    for (int mp = 0; mp < 16; mp++) {
        float2 v = up2(acc[mp]);
        prow[(size_t)(2 * mp) * N]     = v.x;
        prow[(size_t)(2 * mp + 1) * N] = v.y;
    }
}

// ---------------- init skinny: [h0|c0] = mean @ [Wh|Wc], KS=32 -------------
__global__ void init_part(const float* __restrict__ Wh,
                          const float* __restrict__ Wc) {
    __shared__ __align__(16) float xs[64 * 34];
    int kBeg = blockIdx.y * 64;
    for (int i = threadIdx.x; i < 32 * 64; i += 256) {
        int m = i >> 6, kk = i & 63;
        xs[kk * 34 + m] = g_mean[m * 2048 + kBeg + kk];
    }
    __syncthreads();
    int n = blockIdx.x * 256 + threadIdx.x;    // < 1024
    const float* W = (n < 512) ? (Wh + (size_t)kBeg * 512 + n)
                               : (Wc + (size_t)kBeg * 512 + (n - 512));
    skinny_body(xs, W, 512, 64,
                g_part + (size_t)(blockIdx.y * 32) * 1024 + n, 1024);
}

__global__ void reduce_init_hc(const float* __restrict__ init_h_b,
                               const float* __restrict__ init_c_b) {
    int idx = blockIdx.x * blockDim.x + threadIdx.x;   // 32*1024
    if (idx >= 32 * 1024) return;
    int m = idx >> 10, n = idx & 1023;
    float s = 0.f;
#pragma unroll 8
    for (int ks = 0; ks < 32; ks++) s += g_part[((size_t)(ks * 32 + m)) * 1024 + n];
    if (n < 512) {
        float v = s + init_h_b[n];
        g_h[m * 512 + n] = v;
        g_x[m * 3072 + 2560 + n] = v;
    } else {
        g_c[m * 512 + (n - 512)] = s + init_c_b[n - 512];
    }
}

// ---------------- att1 = enc_sorted @ enc_att_w + b via tf32 MMA -----------
// block tile 128m x 64n, BK=16, 8 warps (2m x 4n m16n8 tiles per warp)
__global__ void __launch_bounds__(256) att1_tc(const float* __restrict__ enc,
                                               const float* __restrict__ W,
                                               const float* __restrict__ bias) {
    __shared__ unsigned As[128][37];
    __shared__ unsigned Bs[64][21];
    int tid = threadIdx.x;
    int warp = tid >> 5, lane = tid & 31;
    int bm = blockIdx.x * 128, bn = blockIdx.y * 64;
    int wm = (warp & 3) * 32, wn = (warp >> 2) * 32;
    int row = lane >> 2, tig = lane & 3;

    // staging assignments for A: thread covers rows m0 and m0+64, k quad kq4
    int m0 = tid >> 2;
    int kq4 = (tid & 3) * 4;
    const float* arow0; const float* arow1;
    {
        int gm = bm + m0; int b = gm / 196, p = gm - b * 196;
        arow0 = enc + ((size_t)g_sort[b] * Pp + p) * Dd + kq4;
        gm = bm + m0 + 64; b = gm / 196; p = gm - b * 196;
        arow1 = enc + ((size_t)g_sort[b] * Pp + p) * Dd + kq4;
    }

    float acc[2][4][4];
#pragma unroll
    for (int i = 0; i < 2; i++)
#pragma unroll
        for (int j = 0; j < 4; j++)
#pragma unroll
            for (int q = 0; q < 4; q++) acc[i][j][q] = 0.f;

    for (int k0 = 0; k0 < Dd; k0 += 16) {
        float4 va = *(const float4*)(arow0 + k0);
        As[m0][kq4 + 0] = tf32of(va.x);
        As[m0][kq4 + 1] = tf32of(va.y);
        As[m0][kq4 + 2] = tf32of(va.z);
        As[m0][kq4 + 3] = tf32of(va.w);
        va = *(const float4*)(arow1 + k0);
        As[m0 + 64][kq4 + 0] = tf32of(va.x);
        As[m0 + 64][kq4 + 1] = tf32of(va.y);
        As[m0 + 64][kq4 + 2] = tf32of(va.z);
        As[m0 + 64][kq4 + 3] = tf32of(va.w);
#pragma unroll
        for (int i = 0; i < 4; i++) {
            int idx = tid + i * 256;
            int kk = idx >> 6, n = idx & 63;
            Bs[n][kk] = tf32of(W[(size_t)(k0 + kk) * Aa + bn + n]);
        }
        __syncthreads();
#pragma unroll
        for (int ks = 0; ks < 2; ks++) {
            int kb = ks * 8;
            unsigned b0[4], b1[4];
#pragma unroll
            for (int nt = 0; nt < 4; nt++) {
                int n = wn + nt * 8 + row;
                b0[nt] = Bs[n][kb + tig];
                b1[nt] = Bs[n][kb + tig + 4];
            }
#pragma unroll
            for (int mt = 0; mt < 2; mt++) {
                int m = wm + mt * 16;
                unsigned a0 = As[m + row][kb + tig];
                unsigned a1 = As[m + row + 8][kb + tig];
                unsigned a2 = As[m + row][kb + tig + 4];
                unsigned a3 = As[m + row + 8][kb + tig + 4];
#pragma unroll
                for (int nt = 0; nt < 4; nt++)
                    mma_tf32(acc[mt][nt], a0, a1, a2, a3, b0[nt], b1[nt]);
            }
        }
        __syncthreads();
    }
#pragma unroll
    for (int mt = 0; mt < 2; mt++) {
        int mrow = bm + wm + mt * 16 + row;
#pragma unroll
        for (int nt = 0; nt < 4; nt++) {
            int col = bn + wn + nt * 8 + 2 * tig;
            float b0v = bias[col], b1v = bias[col + 1];
            g_att1[(size_t)mrow * Aa + col]           = acc[mt][nt][0] + b0v;
            g_att1[(size_t)mrow * Aa + col + 1]       = acc[mt][nt][1] + b1v;
            g_att1[(size_t)(mrow + 8) * Aa + col]     = acc[mt][nt][2] + b0v;
            g_att1[(size_t)(mrow + 8) * Aa + col + 1] = acc[mt][nt][3] + b1v;
        }
    }
}

// ---------------- persistent kernel: entire 20-step decode loop ------------
__global__ void __launch_bounds__(256, 2) loop_kernel(
    const float* __restrict__ enc,
    const float* __restrict__ dec_att_w, const float* __restrict__ dec_att_b,
    const float* __restrict__ f_beta_w,  const float* __restrict__ f_beta_b,
    const float* __restrict__ full_w,    const float* __restrict__ full_b,
    const float* __restrict__ lstm_w_ih, const float* __restrict__ lstm_w_hh,
    const float* __restrict__ lstm_b,
    float* __restrict__ out)
{
    __shared__ __align__(16) float sb[4352];
    __shared__ float red[16];
    const int bid = blockIdx.x, tid = threadIdx.x;
    const int warp = tid >> 5, lane = tid & 31;
    const unsigned G = 256;
    unsigned tgt = 0;

    for (int t = 0; t < Tt; t++) {
        // ---- P1: [att2|gate] parts = h @ [dec_att_w | f_beta_w], KS=8 -----
        if (bid < 80) {
            int nx = bid % 10, ky = bid / 10;
            int kBeg = ky * 64;
            for (int i = tid; i < 32 * 64; i += 256) {
                int m = i >> 6, kk = i & 63;
                sb[kk * 34 + m] = g_h[m * 512 + kBeg + kk];
            }
            __syncthreads();
            int n = nx * 256 + tid;
            const float* W; int st;
            if (n < 512) { W = dec_att_w + (size_t)kBeg * 512 + n; st = 512; }
            else         { W = f_beta_w + (size_t)kBeg * 2048 + (n - 512); st = 2048; }
            skinny_body(sb, W, st, 64,
                        g_part + (size_t)(ky * 32) * 2560 + n, 2560);
        }
        gsync(tgt += G);

        // ---- P2: attention scores -> g_escore (256 blocks: b x pchunk) ----
        {
            int b = bid >> 3, pc = bid & 7;
#pragma unroll
            for (int rep = 0; rep < 2; rep++) {
                int aa = rep * 256 + tid;
                float s = dec_att_b[aa];
#pragma unroll
                for (int ks = 0; ks < 8; ks++)
                    s += g_part[(size_t)(ks * 32 + b) * 2560 + aa];
                sb[aa] = s;               // t2s in [0,512)
                sb[512 + aa] = full_w[aa];
            }
            __syncthreads();
            float fb = *full_b;
            int pbeg = pc * 25;
            int pend = min(196, pbeg + 25);
            for (int p = pbeg + warp; p < pend; p += 8) {
                const float4* rowp = (const float4*)(g_att1 + (size_t)(b * 196 + p) * 512);
                float s = 0.f;
#pragma unroll
                for (int a4 = lane; a4 < 128; a4 += 32) {
                    float4 v = rowp[a4];
                    float4 tt = *(const float4*)&sb[a4 * 4];
                    float4 w = *(const float4*)&sb[512 + a4 * 4];
                    s += fmaxf(v.x + tt.x, 0.f) * w.x;
                    s += fmaxf(v.y + tt.y, 0.f) * w.y;
                    s += fmaxf(v.z + tt.z, 0.f) * w.z;
                    s += fmaxf(v.w + tt.w, 0.f) * w.w;
                }
#pragma unroll
                for (int o = 16; o; o >>= 1) s += __shfl_down_sync(0xffffffffu, s, o);
                if (lane == 0) g_escore[b * 196 + p] = s + fb;
            }
        }
        gsync(tgt += G);

        // ---- P3: softmax (redundant per block) + gate + awe -> x ----------
        {
            int b = bid >> 3, dc = bid & 7;
            int sbt = g_sort[b];
            float e = (tid < 196) ? g_escore[b * 196 + tid] : -FLT_MAX;
            float m = e;
#pragma unroll
            for (int o = 16; o; o >>= 1)
                m = fmaxf(m, __shfl_xor_sync(0xffffffffu, m, o));
            if (lane == 0) red[warp] = m;
            __syncthreads();
            if (tid == 0) {
                float mm = red[0];
#pragma unroll
                for (int i = 1; i < 8; i++) mm = fmaxf(mm, red[i]);
                red[8] = mm;
            }
            __syncthreads();
            float mx = red[8];
            float ex = (tid < 196) ? expf(e - mx) : 0.f;
            float ss = ex;
#pragma unroll
            for (int o = 16; o; o >>= 1) ss += __shfl_xor_sync(0xffffffffu, ss, o);
            if (lane == 0) red[warp] = ss;
            __syncthreads();
            if (tid == 0) {
                float s2 = 0.f;
#pragma unroll
                for (int i = 0; i < 8; i++) s2 += red[i];
                red[9] = s2;
            }
            __syncthreads();
            float inv = 1.f / red[9];
            if (tid < 196) sb[tid] = ex * inv;   // alpha
            __syncthreads();
            int active = (t < g_declen[b]);
            if (dc == 0 && tid < 196)
                out[OUT_ALPHA + (size_t)(b * Tt + t) * 196 + tid] =
                    active ? sb[tid] : 0.f;
            int d = dc * 256 + tid;
            float gp = f_beta_b[d];
#pragma unroll
            for (int ks = 0; ks < 8; ks++)
                gp += g_part[(size_t)(ks * 32 + b) * 2560 + 512 + d];
            float gate = sigf(gp);
            const float* base = enc + (size_t)sbt * Pp * Dd + d;
            float s0 = 0.f, s1 = 0.f;
#pragma unroll 2
            for (int p = 0; p < 196; p += 2) {
                s0 += base[(size_t)p * Dd] * sb[p];
                s1 += base[(size_t)(p + 1) * Dd] * sb[p + 1];
            }
            g_x[b * 3072 + 512 + d] = (s0 + s1) * gate;
        }
        gsync(tgt += G);

        // ---- P4: lstm gates parts = x @ [w_ih;w_hh], KS=24 (192 blocks) ---
        if (bid < 192) {
            int nx = bid & 7, ky = bid >> 3;
            int kBeg = ky * 128;
            for (int i = tid; i < 32 * 128; i += 256) {
                int m = i >> 7, kk = i & 127;
                sb[kk * 34 + m] = g_x[m * 3072 + kBeg + kk];
            }
            __syncthreads();
            int n = nx * 256 + tid;
            const float* W = (kBeg < 2560)
                ? (lstm_w_ih + (size_t)kBeg * 2048 + n)
                : (lstm_w_hh + (size_t)(kBeg - 2560) * 2048 + n);
            skinny_body(sb, W, 2048, 128,
                        g_part + (size_t)(ky * 32) * 2048 + n, 2048);
        }
        gsync(tgt += G);

        // ---- P5: LSTM cell (64 blocks) ------------------------------------
        if (bid < 64) {
            int idx = bid * 256 + tid;
            int b = idx >> 9, j = idx & 511;
            float s[4];
#pragma unroll
            for (int g = 0; g < 4; g++) {
                int n = g * 512 + j;
                float acc = lstm_b[n];
#pragma unroll 8
                for (int ks = 0; ks < 24; ks++)
                    acc += g_part[(size_t)(ks * 32 + b) * 2048 + n];
                s[g] = acc;
            }
            float c_old = g_c[idx];
            float c_new = sigf(s[1]) * c_old + sigf(s[0]) * tanhf(s[2]);
            float h_new = sigf(s[3]) * tanhf(c_new);
            g_hall[((size_t)t * Bt + b) * Hh + j] = h_new;
            int active = (t < g_declen[b]);
            float h_keep = active ? h_new : g_h[idx];
            float c_keep = active ? c_new : c_old;
            g_h[idx] = h_keep;
            g_c[idx] = c_keep;
            g_x[b * 3072 + 2560 + j] = h_keep;
            if (t + 1 < Tt)
                g_x[b * 3072 + j] = g_embs[((size_t)b * Tt + (t + 1)) * Ee + j];
        }
        gsync(tgt += G);
    }
}

// ---------------- deferred fc via tf32 MMA: preds = h_all @ fc_w + b -------
// block tile 128m x 64n, BK=16. M=640, N=10000, K=512.
__global__ void __launch_bounds__(256) fc_tc(const float* __restrict__ fc_w,
                                             const float* __restrict__ fc_b,
                                             float* __restrict__ out) {
    __shared__ unsigned As[128][37];
    __shared__ unsigned Bs[64][21];
    int tid = threadIdx.x;
    int warp = tid >> 5, lane = tid & 31;
    int bm = blockIdx.x * 128, bn = blockIdx.y * 64;
    int wm = (warp & 3) * 32, wn = (warp >> 2) * 32;
    int row = lane >> 2, tig = lane & 3;

    int m0 = tid >> 2;
    int kq4 = (tid & 3) * 4;
    const float* arow0 = g_hall + (size_t)(bm + m0) * Hh + kq4;
    const float* arow1 = g_hall + (size_t)(bm + m0 + 64) * Hh + kq4;

    float acc[2][4][4];
#pragma unroll
    for (int i = 0; i < 2; i++)
#pragma unroll
        for (int j = 0; j < 4; j++)
#pragma unroll
            for (int q = 0; q < 4; q++) acc[i][j][q] = 0.f;

    for (int k0 = 0; k0 < Hh; k0 += 16) {
        float4 va = *(const float4*)(arow0 + k0);
        As[m0][kq4 + 0] = tf32of(va.x);
        As[m0][kq4 + 1] = tf32of(va.y);
        As[m0][kq4 + 2] = tf32of(va.z);
        As[m0][kq4 + 3] = tf32of(va.w);
        va = *(const float4*)(arow1 + k0);
        As[m0 + 64][kq4 + 0] = tf32of(va.x);
        As[m0 + 64][kq4 + 1] = tf32of(va.y);
        As[m0 + 64][kq4 + 2] = tf32of(va.z);
        As[m0 + 64][kq4 + 3] = tf32of(va.w);
#pragma unroll
        for (int i = 0; i < 4; i++) {
            int idx = tid + i * 256;
            int kk = idx >> 6, n = idx & 63;
            int gn = bn + n;
            Bs[n][kk] = (gn < Vv) ? tf32of(fc_w[(size_t)(k0 + kk) * Vv + gn]) : 0u;
        }
        __syncthreads();
#pragma unroll
        for (int ks = 0; ks < 2; ks++) {
            int kb = ks * 8;
            unsigned b0[4], b1[4];
#pragma unroll
            for (int nt = 0; nt < 4; nt++) {
                int n = wn + nt * 8 + row;
                b0[nt] = Bs[n][kb + tig];
                b1[nt] = Bs[n][kb + tig + 4];
            }
#pragma unroll
            for (int mt = 0; mt < 2; mt++) {
                int m = wm + mt * 16;
                unsigned a0 = As[m + row][kb + tig];
                unsigned a1 = As[m + row + 8][kb + tig];
                unsigned a2 = As[m + row][kb + tig + 4];
                unsigned a3 = As[m + row + 8][kb + tig + 4];
#pragma unroll
                for (int nt = 0; nt < 4; nt++)
                    mma_tf32(acc[mt][nt], a0, a1, a2, a3, b0[nt], b1[nt]);
            }
        }
        __syncthreads();
    }
#pragma unroll
    for (int mt = 0; mt < 2; mt++) {
#pragma unroll
        for (int rr = 0; rr < 2; rr++) {
            int m = bm + wm + mt * 16 + row + rr * 8;   // m = t*32 + b
            int t = m >> 5, b = m & 31;
            int active = (t < g_declen[b]);
            size_t obase = OUT_PRED + ((size_t)b * Tt + t) * Vv;
#pragma unroll
            for (int nt = 0; nt < 4; nt++) {
                int col = bn + wn + nt * 8 + 2 * tig;
                if (col >= Vv) continue;
                float v0 = acc[mt][nt][2 * rr + 0];
                float v1 = acc[mt][nt][2 * rr + 1];
                out[obase + col]     = active ? (v0 + fc_b[col]) : 0.f;
                if (col + 1 < Vv)
                    out[obase + col + 1] = active ? (v1 + fc_b[col + 1]) : 0.f;
            }
        }
    }
}

// ---------------- launch ----------------------------------------------------
extern "C" void kernel_launch(void* const* d_in, const int* in_sizes, int n_in,
                              void* d_out, int out_size) {
    const float* enc        = (const float*)d_in[0];
    const int*   caps_in    = (const int*)d_in[1];
    const int*   caplen     = (const int*)d_in[2];
    const float* enc_att_w  = (const float*)d_in[3];
    const float* enc_att_b  = (const float*)d_in[4];
    const float* dec_att_w  = (const float*)d_in[5];
    const float* dec_att_b  = (const float*)d_in[6];
    const float* full_att_w = (const float*)d_in[7];
    const float* full_att_b = (const float*)d_in[8];
    const float* emb        = (const float*)d_in[9];
    const float* init_h_w   = (const float*)d_in[10];
    const float* init_h_b   = (const float*)d_in[11];
    const float* init_c_w   = (const float*)d_in[12];
    const float* init_c_b   = (const float*)d_in[13];
    const float* f_beta_w   = (const float*)d_in[14];
    const float* f_beta_b   = (const float*)d_in[15];
    const float* lstm_w_ih  = (const float*)d_in[16];
    const float* lstm_w_hh  = (const float*)d_in[17];
    const float* lstm_b     = (const float*)d_in[18];
    const float* fc_w       = (const float*)d_in[19];
    const float* fc_b       = (const float*)d_in[20];
    float* out = (float*)d_out;

    setup_kernel<<<1, 32>>>(caplen, caps_in, out);
    emb_gather<<<1280, 256>>>(emb);
    mean_kernel<<<dim3(8, 32), 256>>>(enc);

    // fused [h0|c0] = mean @ [init_h_w|init_c_w]  (K=2048, N=1024, KS=32)
    init_part<<<dim3(4, 32), 256>>>(init_h_w, init_c_w);
    reduce_init_hc<<<128, 256>>>(init_h_b, init_c_b);

    // att1 = enc_sorted @ enc_att_w + b   (6272 x 512, K=2048) via tf32 MMA
    att1_tc<<<dim3(49, 8), 256>>>(enc, enc_att_w, enc_att_b);

    // whole 20-step decode loop as one persistent kernel
    reset_bar<<<1, 1>>>();
    loop_kernel<<<256, 256>>>(enc,
                              dec_att_w, dec_att_b,
                              f_beta_w, f_beta_b,
                              full_att_w, full_att_b,
                              lstm_w_ih, lstm_w_hh, lstm_b,
                              out);

    // preds = h_all @ fc_w + b (masked), one big tf32 GEMM after the loop
    fc_tc<<<dim3(5, 157), 256>>>(fc_w, fc_b, out);
}